// round 14
// baseline (speedup 1.0000x reference)
#include <cuda_runtime.h>
#include <cuda_bf16.h>
#include <mma.h>
#include <math.h>
#include <cstdint>

using namespace nvcuda;

// ---------------------------------------------------------------------------
// Problem constants
// ---------------------------------------------------------------------------
namespace {
constexpr int B  = 4;
constexpr int C  = 256;
constexpr int H  = 128;
constexpr int W  = 128;
constexpr int HW = H * W;          // 16384
constexpr int NC = 19;
constexpr int HD = 32;
constexpr int C4 = 4 * C;          // 1024
constexpr float SCALE = 0.17677669529663687f;
constexpr float EPS = 1e-5f;
}

// ---------------------------------------------------------------------------
// Scratch
// ---------------------------------------------------------------------------
__device__ __nv_bfloat16 g_queryb[B * C * HW];
__device__ __nv_bfloat16 g_fusedb[B * C * HW];
__device__ float g_mask [B * NC * HW];
__device__ __nv_bfloat16 g_xab [B * C * HW];
__device__ float g_weff [NC * C];
__device__ float g_cf   [B * NC * C];
__device__ float g_kbuf [B * NC * C];
__device__ float g_vbuf [B * NC * C];
__device__ float g_outb [B * C * HW];
__device__ __nv_bfloat16 g_qdb  [B * C * HW];
__device__ __nv_bfloat16 g_qqb  [B * C * HW];
__device__ __nv_bfloat16 g_attb [B * C * HW];
__device__ __nv_bfloat16 g_yb   [B * C * HW];
__device__ __nv_bfloat16 g_hidb [B * C4 * HW];
__device__ __nv_bfloat16 g_hid2b[B * C4 * HW];
__device__ __nv_bfloat16 g_wqpwb [C * C];
__device__ __nv_bfloat16 g_wprojb[C * C];
__device__ __nv_bfloat16 g_wmlp1b[C4 * C];
__device__ __nv_bfloat16 g_wmlp2b[C * C4];

// ---------------------------------------------------------------------------
// helpers
// ---------------------------------------------------------------------------
__device__ __forceinline__ uint32_t smem_u32(const void* p) {
    uint32_t a;
    asm("{ .reg .u64 t; cvta.to.shared.u64 t, %1; cvt.u32.u64 %0, t; }" : "=r"(a) : "l"(p));
    return a;
}
__device__ __forceinline__ void cp_async16(uint32_t saddr, const void* gaddr) {
    asm volatile("cp.async.cg.shared.global [%0], [%1], 16;" :: "r"(saddr), "l"(gaddr));
}
#define CP_COMMIT() asm volatile("cp.async.commit_group;" ::: "memory")
#define CP_WAIT(n)  asm volatile("cp.async.wait_group %0;" :: "n"(n) : "memory")

// ---------------------------------------------------------------------------
// Fused fp32 -> bf16 conversion for all four weight tensors (one launch)
// ---------------------------------------------------------------------------
__global__ void wconv_kernel(const float* __restrict__ w_q_pw, const float* __restrict__ w_proj,
                             const float* __restrict__ w_mlp1, const float* __restrict__ w_mlp2)
{
    int i = blockIdx.x * 256 + threadIdx.x;
    constexpr int N1 = C * C;            // 65536
    constexpr int N2 = 2 * C * C;        // 131072
    constexpr int N3 = N2 + C4 * C;      // 393216
    constexpr int N4 = N3 + C * C4;      // 655360
    if (i < N1)       g_wqpwb [i]      = __float2bfloat16(w_q_pw[i]);
    else if (i < N2)  g_wprojb[i - N1] = __float2bfloat16(w_proj[i - N1]);
    else if (i < N3)  g_wmlp1b[i - N2] = __float2bfloat16(w_mlp1[i - N2]);
    else if (i < N4)  g_wmlp2b[i - N3] = __float2bfloat16(w_mlp2[i - N3]);
}

// ---------------------------------------------------------------------------
// K1: LN(low) -> query(bf16) ; LN(high) ; fused(bf16) = 0.5*(q + ln_high)
// ---------------------------------------------------------------------------
__global__ void ln_fuse_kernel(const float* __restrict__ low, const float* __restrict__ high,
                               const float* __restrict__ gl, const float* __restrict__ bl,
                               const float* __restrict__ gh, const float* __restrict__ bh)
{
    int pos = blockIdx.x * blockDim.x + threadIdx.x;
    if (pos >= B * HW) return;
    int b = pos / HW, l = pos % HW;
    const float* lp = low  + (size_t)b * C * HW + l;
    const float* hp = high + (size_t)b * C * HW + l;
    float s1 = 0.f, s2 = 0.f, t1 = 0.f, t2 = 0.f;
    #pragma unroll 8
    for (int c = 0; c < C; c++) {
        float a = lp[(size_t)c * HW]; s1 += a; s2 += a * a;
        float e = hp[(size_t)c * HW]; t1 += e; t2 += e * e;
    }
    float mu1 = s1 * (1.f / C), mu2 = t1 * (1.f / C);
    float i1 = rsqrtf(s2 * (1.f / C) - mu1 * mu1 + EPS);
    float i2 = rsqrtf(t2 * (1.f / C) - mu2 * mu2 + EPS);
    __nv_bfloat16* qo = g_queryb + (size_t)b * C * HW + l;
    __nv_bfloat16* fo = g_fusedb + (size_t)b * C * HW + l;
    #pragma unroll 8
    for (int c = 0; c < C; c++) {
        float q = (lp[(size_t)c * HW] - mu1) * i1 * gl[c] + bl[c];
        float k = (hp[(size_t)c * HW] - mu2) * i2 * gh[c] + bh[c];
        qo[(size_t)c * HW] = __float2bfloat16(q);
        fo[(size_t)c * HW] = __float2bfloat16(0.5f * (q + k));
    }
}

// LN over channels -> bf16 out
__global__ void ln_bf_kernel(const float* __restrict__ in, __nv_bfloat16* __restrict__ out,
                             const float* __restrict__ g, const float* __restrict__ bb)
{
    int pos = blockIdx.x * blockDim.x + threadIdx.x;
    if (pos >= B * HW) return;
    int b = pos / HW, l = pos % HW;
    const float* ip = in + (size_t)b * C * HW + l;
    float s1 = 0.f, s2 = 0.f;
    #pragma unroll 8
    for (int c = 0; c < C; c++) { float a = ip[(size_t)c * HW]; s1 += a; s2 += a * a; }
    float mu = s1 * (1.f / C);
    float iv = rsqrtf(s2 * (1.f / C) - mu * mu + EPS);
    __nv_bfloat16* op = out + (size_t)b * C * HW + l;
    #pragma unroll 8
    for (int c = 0; c < C; c++)
        op[(size_t)c * HW] = __float2bfloat16((ip[(size_t)c * HW] - mu) * iv * g[c] + bb[c]);
}

// ---------------------------------------------------------------------------
// K2: compose mask-path weights
// ---------------------------------------------------------------------------
__global__ void weff_kernel(const float* __restrict__ w_ml2, const float* __restrict__ w_ml1)
{
    int n = blockIdx.x, ci = threadIdx.x;
    int g = ci >> 6, jj = ci & 63;
    float acc = 0.f;
    #pragma unroll
    for (int j = 0; j < 64; j++) {
        int m = g * 64 + j;
        acc += w_ml2[n * C + m] * w_ml1[m * 64 + jj];
    }
    g_weff[n * C + ci] = acc;
}

// ---------------------------------------------------------------------------
// K3 v2: mask logits + grouped align conv — 2 positions per thread
// ---------------------------------------------------------------------------
__global__ __launch_bounds__(128) void mask_xa_kernel(const float* __restrict__ w_align)
{
    extern __shared__ float sm[];
    float* weff_s = sm;
    float* wal_s  = sm + NC * C;
    int tid = threadIdx.x;
    for (int i = tid; i < NC * C; i += 128) weff_s[i] = g_weff[i];
    for (int i = tid; i < C * 64; i += 128) wal_s[i] = w_align[i];
    __syncthreads();
    int b = blockIdx.y;
    int l0 = blockIdx.x * 256 + tid;
    int l1 = l0 + 128;
    const __nv_bfloat16* fb = g_fusedb + (size_t)b * C * HW;
    float m0[NC], m1[NC];
    #pragma unroll
    for (int n = 0; n < NC; n++) { m0[n] = 0.f; m1[n] = 0.f; }
    for (int g = 0; g < 4; g++) {
        float f0[64], f1[64];
        #pragma unroll
        for (int j = 0; j < 64; j++) {
            size_t co = (size_t)(g * 64 + j) * HW;
            f0[j] = __bfloat162float(fb[co + l0]);
            f1[j] = __bfloat162float(fb[co + l1]);
        }
        for (int n = 0; n < NC; n++) {
            const float* wr = weff_s + n * C + g * 64;
            float a0 = 0.f, a1 = 0.f;
            #pragma unroll
            for (int j = 0; j < 64; j++) { float w = wr[j]; a0 += w * f0[j]; a1 += w * f1[j]; }
            m0[n] += a0; m1[n] += a1;
        }
        for (int co = 0; co < 64; co++) {
            const float* wr = wal_s + (g * 64 + co) * 64;
            float a0 = 0.f, a1 = 0.f;
            #pragma unroll
            for (int j = 0; j < 64; j++) { float w = wr[j]; a0 += w * f0[j]; a1 += w * f1[j]; }
            size_t o = (size_t)b * C * HW + (size_t)(g * 64 + co) * HW;
            g_xab[o + l0] = __float2bfloat16(a0);
            g_xab[o + l1] = __float2bfloat16(a1);
        }
    }
    #pragma unroll
    for (int n = 0; n < NC; n++) {
        size_t o = (size_t)b * NC * HW + (size_t)n * HW;
        g_mask[o + l0] = m0[n];
        g_mask[o + l1] = m1[n];
    }
}

// ---------------------------------------------------------------------------
// K4: spatial softmax over HW per (b,nc)
// ---------------------------------------------------------------------------
__global__ void softmax_hw_kernel()
{
    __shared__ float red[256];
    int row = blockIdx.x;
    float* p = g_mask + (size_t)row * HW;
    int tid = threadIdx.x;
    float m = -1e30f;
    for (int i = tid; i < HW; i += 256) m = fmaxf(m, p[i]);
    red[tid] = m; __syncthreads();
    for (int s = 128; s > 0; s >>= 1) { if (tid < s) red[tid] = fmaxf(red[tid], red[tid + s]); __syncthreads(); }
    m = red[0]; __syncthreads();
    float s = 0.f;
    for (int i = tid; i < HW; i += 256) s += expf(p[i] - m);
    red[tid] = s; __syncthreads();
    for (int st = 128; st > 0; st >>= 1) { if (tid < st) red[tid] += red[tid + st]; __syncthreads(); }
    float inv = 1.f / red[0];
    for (int i = tid; i < HW; i += 256) p[i] = expf(p[i] - m) * inv;
}

// ---------------------------------------------------------------------------
// K5 v2: cf[b,n,c] — 8 channels per block
// ---------------------------------------------------------------------------
__global__ __launch_bounds__(256) void cf_kernel()
{
    int c0 = blockIdx.x * 8, b = blockIdx.y;
    int tid = threadIdx.x;
    const __nv_bfloat16* xp = g_xab + (size_t)(b * C + c0) * HW;
    const float* mp = g_mask + (size_t)b * NC * HW;
    float acc[NC][8];
    #pragma unroll
    for (int n = 0; n < NC; n++)
        #pragma unroll
        for (int cc = 0; cc < 8; cc++) acc[n][cc] = 0.f;
    for (int l = tid; l < HW; l += 256) {
        float xv[8];
        #pragma unroll
        for (int cc = 0; cc < 8; cc++) xv[cc] = __bfloat162float(xp[(size_t)cc * HW + l]);
        #pragma unroll
        for (int n = 0; n < NC; n++) {
            float m = mp[(size_t)n * HW + l];
            #pragma unroll
            for (int cc = 0; cc < 8; cc++) acc[n][cc] += m * xv[cc];
        }
    }
    __shared__ float red[8][NC * 8];
    int lane = tid & 31, wd = tid >> 5;
    #pragma unroll
    for (int n = 0; n < NC; n++)
        #pragma unroll
        for (int cc = 0; cc < 8; cc++) {
            float v = acc[n][cc];
            #pragma unroll
            for (int off = 16; off > 0; off >>= 1) v += __shfl_down_sync(0xFFFFFFFFu, v, off);
            if (lane == 0) red[wd][n * 8 + cc] = v;
        }
    __syncthreads();
    if (tid < NC * 8) {
        float s = 0.f;
        #pragma unroll
        for (int w = 0; w < 8; w++) s += red[w][tid];
        int n = tid >> 3, cc = tid & 7;
        g_cf[((size_t)b * NC + n) * C + c0 + cc] = s;
    }
}

// ---------------------------------------------------------------------------
// K6: memory-mix + kv projection
// ---------------------------------------------------------------------------
__global__ void kv_kernel(const float* __restrict__ w_kv, const float* __restrict__ b_kv,
                          const float* __restrict__ memory)
{
    int row = blockIdx.x;
    int n = row % NC;
    int tid = threadIdx.x;
    __shared__ float cfs[C];
    if (tid < C) cfs[tid] = 0.9f * g_cf[(size_t)row * C + tid] + 0.1f * memory[n * C + tid];
    __syncthreads();
    float acc = b_kv[tid];
    #pragma unroll 8
    for (int c = 0; c < C; c++) acc += cfs[c] * w_kv[(size_t)tid * C + c];
    if (tid < C) g_kbuf[(size_t)row * C + tid] = acc;
    else         g_vbuf[(size_t)row * C + tid - C] = acc;
}

// ---------------------------------------------------------------------------
// Depthwise 3x3 tiled
// ---------------------------------------------------------------------------
__device__ __forceinline__ float ldf(const float* p) { return *p; }
__device__ __forceinline__ float ldf(const __nv_bfloat16* p) { return __bfloat162float(*p); }

template <typename Tin, typename Tout, bool GELU>
__global__ __launch_bounds__(256) void dw3x3t_kernel(
    const Tin* __restrict__ in, Tout* __restrict__ out,
    const float* __restrict__ w, const float* __restrict__ bias, int Cn)
{
    __shared__ float tile[10][132];
    int bc = blockIdx.x;
    int y0 = blockIdx.y * 8;
    int c = bc % Cn;
    const Tin* ip = in + (size_t)bc * HW;
    int tid = threadIdx.x;
    #pragma unroll
    for (int i = tid; i < 10 * 132; i += 256) {
        int ry = i / 132, rx = i % 132;
        int gy = y0 - 1 + ry, gx = rx - 1;
        float v = 0.f;
        if (gy >= 0 && gy < H && gx >= 0 && gx < W) v = ldf(ip + gy * W + gx);
        tile[ry][rx] = v;
    }
    __syncthreads();
    float w0 = w[c*9+0], w1 = w[c*9+1], w2 = w[c*9+2];
    float w3 = w[c*9+3], w4 = w[c*9+4], w5 = w[c*9+5];
    float w6 = w[c*9+6], w7 = w[c*9+7], w8 = w[c*9+8];
    float bv = bias[c];
    int tx = tid & 31, ty = tid >> 5;
    int xb = tx * 4;
    float acc[4] = { bv, bv, bv, bv };
    {
        const float* r0 = tile[ty + 0];
        const float* r1 = tile[ty + 1];
        const float* r2 = tile[ty + 2];
        float v0[6], v1[6], v2[6];
        #pragma unroll
        for (int j = 0; j < 6; j++) { v0[j] = r0[xb+j]; v1[j] = r1[xb+j]; v2[j] = r2[xb+j]; }
        #pragma unroll
        for (int o = 0; o < 4; o++) {
            acc[o] += v0[o]*w0 + v0[o+1]*w1 + v0[o+2]*w2;
            acc[o] += v1[o]*w3 + v1[o+1]*w4 + v1[o+2]*w5;
            acc[o] += v2[o]*w6 + v2[o+1]*w7 + v2[o+2]*w8;
        }
    }
    if (GELU) {
        #pragma unroll
        for (int o = 0; o < 4; o++) {
            float x = acc[o];
            float u = 1.5957691216057308f * (x + 0.044715f * x * x * x);
            float s = 1.f / (1.f + __expf(-u));
            acc[o] = x * s;
        }
    }
    size_t obase = (size_t)bc * HW + (size_t)(y0 + ty) * W + xb;
    if (sizeof(Tout) == 2) {
        __nv_bfloat162 h0 = __floats2bfloat162_rn(acc[0], acc[1]);
        __nv_bfloat162 h1 = __floats2bfloat162_rn(acc[2], acc[3]);
        uint2 pk = { *(uint32_t*)&h0, *(uint32_t*)&h1 };
        *(uint2*)((__nv_bfloat16*)out + obase) = pk;
    } else {
        float4 v = { acc[0], acc[1], acc[2], acc[3] };
        *(float4*)((float*)out + obase) = v;
    }
}

// ---------------------------------------------------------------------------
// Attention v2: 4 positions/thread, vectorized q loads/stores
// ---------------------------------------------------------------------------
__global__ __launch_bounds__(256) void attn_kernel()
{
    __shared__ float ks[NC * C], vs[NC * C];
    int b = blockIdx.y;
    int tid = threadIdx.x;
    for (int i = tid; i < NC * C; i += 256) {
        ks[i] = g_kbuf[(size_t)b * NC * C + i];
        vs[i] = g_vbuf[(size_t)b * NC * C + i];
    }
    __syncthreads();
    int h = tid >> 5, lane = tid & 31;
    int l0 = blockIdx.x * 128 + lane * 4;
    const __nv_bfloat16* qp = g_qqb + (size_t)b * C * HW + (size_t)(h * HD) * HW + l0;
    float a[4][NC];
    #pragma unroll
    for (int p = 0; p < 4; p++)
        #pragma unroll
        for (int n = 0; n < NC; n++) a[p][n] = 0.f;
    #pragma unroll
    for (int d = 0; d < HD; d++) {
        uint2 pk = *(const uint2*)(qp + (size_t)d * HW);
        __nv_bfloat162 q01 = *(__nv_bfloat162*)&pk.x;
        __nv_bfloat162 q23 = *(__nv_bfloat162*)&pk.y;
        float qv[4] = { __bfloat162float(q01.x), __bfloat162float(q01.y),
                        __bfloat162float(q23.x), __bfloat162float(q23.y) };
        const float* kd = ks + h * HD + d;
        #pragma unroll
        for (int n = 0; n < NC; n++) {
            float kv = kd[n * C];
            #pragma unroll
            for (int p = 0; p < 4; p++) a[p][n] += qv[p] * kv;
        }
    }
    float inv[4];
    #pragma unroll
    for (int p = 0; p < 4; p++) {
        float mn = 1e30f;
        #pragma unroll
        for (int n = 0; n < NC; n++) { a[p][n] *= SCALE; mn = fminf(mn, a[p][n]); }
        float s = 0.f;
        #pragma unroll
        for (int n = 0; n < NC; n++) { a[p][n] = expf(mn - a[p][n]); s += a[p][n]; }
        inv[p] = 1.f / s;
    }
    __nv_bfloat16* op = g_attb + (size_t)b * C * HW + (size_t)(h * HD) * HW + l0;
    #pragma unroll
    for (int d = 0; d < HD; d++) {
        const float* vd = vs + h * HD + d;
        float acc[4] = { 0.f, 0.f, 0.f, 0.f };
        #pragma unroll
        for (int n = 0; n < NC; n++) {
            float vv = vd[n * C];
            #pragma unroll
            for (int p = 0; p < 4; p++) acc[p] += a[p][n] * vv;
        }
        __nv_bfloat162 h0 = __floats2bfloat162_rn(acc[0] * inv[0], acc[1] * inv[1]);
        __nv_bfloat162 h1 = __floats2bfloat162_rn(acc[2] * inv[2], acc[3] * inv[3]);
        uint2 pk = { *(uint32_t*)&h0, *(uint32_t*)&h1 };
        *(uint2*)(op + (size_t)d * HW) = pk;
    }
}

// ---------------------------------------------------------------------------
// WMMA bf16 GEMM, compile-time K: Y = W @ X (+bias)(+res)
// Block tile 128(M) x 256(N), BK=32, cp.async double-buffer, 8 warps (2x4),
// warp tile 64x64. grid = (HW/256, M/128, B)
// ---------------------------------------------------------------------------
constexpr int LDA = 40;
constexpr int LDB = 264;
constexpr int A_BUF = 128 * LDA;
constexpr int B_BUF = 32 * LDB;
constexpr int GEMM_SMEM = (2 * A_BUF + 2 * B_BUF) * 2;

template <int KT, bool OUT_BF16, bool HAS_RES>
__global__ __launch_bounds__(256) void gemm_wmma(
    const __nv_bfloat16* __restrict__ Wb, const __nv_bfloat16* __restrict__ X,
    void* __restrict__ Y, const float* __restrict__ bias, const float* __restrict__ res,
    int M)
{
    constexpr int K = KT;
    constexpr int nk = K >> 5;
    extern __shared__ char smem[];
    __nv_bfloat16* As = (__nv_bfloat16*)smem;
    __nv_bfloat16* Bs = As + 2 * A_BUF;
    uint32_t a_base = smem_u32(As);
    uint32_t b_base = smem_u32(Bs);

    int tid = threadIdx.x;
    int wid = tid >> 5;
    int wm = wid & 1;
    int wn = wid >> 1;
    int n0 = blockIdx.x * 256;
    int bm = blockIdx.y;
    int b  = blockIdx.z;

    const __nv_bfloat16* Ag = Wb + (size_t)(bm * 128) * K;
    const __nv_bfloat16* Xg = X + (size_t)b * K * HW + n0;

    wmma::fragment<wmma::accumulator, 16, 16, 16, float> acc[4][4];
    #pragma unroll
    for (int i = 0; i < 4; i++)
        #pragma unroll
        for (int j = 0; j < 4; j++) wmma::fill_fragment(acc[i][j], 0.f);

    auto load_tile = [&](int kt, int buf) {
        int k0 = kt * 32;
        #pragma unroll
        for (int i = 0; i < 2; i++) {
            int cid = i * 256 + tid;
            int r = cid >> 2, c8 = (cid & 3) * 8;
            cp_async16(a_base + (buf * A_BUF + r * LDA + c8) * 2,
                       Ag + (size_t)r * K + k0 + c8);
        }
        #pragma unroll
        for (int i = 0; i < 4; i++) {
            int cid = i * 256 + tid;
            int r = cid >> 5, c8 = (cid & 31) * 8;
            cp_async16(b_base + (buf * B_BUF + r * LDB + c8) * 2,
                       Xg + (size_t)(k0 + r) * HW + c8);
        }
        CP_COMMIT();
    };

    load_tile(0, 0);

    #pragma unroll
    for (int kt = 0; kt < nk; kt++) {
        int buf = kt & 1;
        if (kt + 1 < nk) { load_tile(kt + 1, buf ^ 1); CP_WAIT(1); }
        else             { CP_WAIT(0); }
        __syncthreads();
        const __nv_bfloat16* Ab = As + buf * A_BUF;
        const __nv_bfloat16* Bb = Bs + buf * B_BUF;
        #pragma unroll
        for (int kk = 0; kk < 2; kk++) {
            wmma::fragment<wmma::matrix_a, 16, 16, 16, __nv_bfloat16, wmma::row_major> af[4];
            #pragma unroll
            for (int i = 0; i < 4; i++)
                wmma::load_matrix_sync(af[i], Ab + (wm * 64 + i * 16) * LDA + kk * 16, LDA);
            #pragma unroll
            for (int j = 0; j < 4; j++) {
                wmma::fragment<wmma::matrix_b, 16, 16, 16, __nv_bfloat16, wmma::row_major> bf;
                wmma::load_matrix_sync(bf, Bb + (kk * 16) * LDB + wn * 64 + j * 16, LDB);
                #pragma unroll
                for (int i = 0; i < 4; i++)
                    wmma::mma_sync(acc[i][j], af[i], bf, acc[i][j]);
            }
        }
        __syncthreads();
    }

    float* stage_w = (float*)smem + wid * (16 * 20);
    int lane = tid & 31;
    int rbase = bm * 128 + wm * 64;
    int cbase = n0 + wn * 64;
    size_t bb0 = (size_t)b * M * HW;
    int r = lane >> 1, cp4 = (lane & 1) * 8;
    #pragma unroll
    for (int i = 0; i < 4; i++) {
        #pragma unroll
        for (int j = 0; j < 4; j++) {
            wmma::store_matrix_sync(stage_w, acc[i][j], 20, wmma::mem_row_major);
            __syncwarp();
            int row = rbase + i * 16 + r;
            float bv = bias[row];
            size_t o = bb0 + (size_t)row * HW + cbase + j * 16 + cp4;
            float4 v0 = *(float4*)(stage_w + r * 20 + cp4);
            float4 v1 = *(float4*)(stage_w + r * 20 + cp4 + 4);
            v0.x += bv; v0.y += bv; v0.z += bv; v0.w += bv;
            v1.x += bv; v1.y += bv; v1.z += bv; v1.w += bv;
            if (HAS_RES) {
                float4 r0 = *(const float4*)(res + o);
                float4 r1 = *(const float4*)(res + o + 4);
                v0.x += r0.x; v0.y += r0.y; v0.z += r0.z; v0.w += r0.w;
                v1.x += r1.x; v1.y += r1.y; v1.z += r1.z; v1.w += r1.w;
            }
            if (OUT_BF16) {
                __nv_bfloat162 h0 = __floats2bfloat162_rn(v0.x, v0.y);
                __nv_bfloat162 h1 = __floats2bfloat162_rn(v0.z, v0.w);
                __nv_bfloat162 h2 = __floats2bfloat162_rn(v1.x, v1.y);
                __nv_bfloat162 h3 = __floats2bfloat162_rn(v1.z, v1.w);
                uint4 pk = { *(uint32_t*)&h0, *(uint32_t*)&h1, *(uint32_t*)&h2, *(uint32_t*)&h3 };
                *(uint4*)((__nv_bfloat16*)Y + o) = pk;
            } else {
                *(float4*)((float*)Y + o) = v0;
                *(float4*)((float*)Y + o + 4) = v1;
            }
            __syncwarp();
        }
    }
}

// ---------------------------------------------------------------------------
// Host launcher
// ---------------------------------------------------------------------------
extern "C" void kernel_launch(void* const* d_in, const int* in_sizes, int n_in,
                              void* d_out, int out_size)
{
    const float* low     = (const float*)d_in[0];
    const float* high    = (const float*)d_in[1];
    const float* gl      = (const float*)d_in[2];
    const float* bl      = (const float*)d_in[3];
    const float* gh      = (const float*)d_in[4];
    const float* bh      = (const float*)d_in[5];
    const float* gm      = (const float*)d_in[6];
    const float* bm      = (const float*)d_in[7];
    const float* w_q_dw  = (const float*)d_in[8];
    const float* b_q_dw  = (const float*)d_in[9];
    const float* w_q_pw  = (const float*)d_in[10];
    const float* b_q_pw  = (const float*)d_in[11];
    const float* w_ml1   = (const float*)d_in[12];
    const float* w_ml2   = (const float*)d_in[13];
    const float* w_align = (const float*)d_in[14];
    const float* w_kv    = (const float*)d_in[15];
    const float* b_kv    = (const float*)d_in[16];
    const float* memory  = (const float*)d_in[17];
    const float* w_proj  = (const float*)d_in[18];
    const float* b_proj  = (const float*)d_in[19];
    const float* w_mlp1  = (const float*)d_in[20];
    const float* b_mlp1  = (const float*)d_in[21];
    const float* w_mlpdw = (const float*)d_in[22];
    const float* b_mlpdw = (const float*)d_in[23];
    const float* w_mlp2  = (const float*)d_in[24];
    const float* b_mlp2  = (const float*)d_in[25];
    float* out = (float*)d_out;

    float *p_out;
    __nv_bfloat16 *p_queryb, *p_qdb, *p_qqb, *p_attb, *p_yb, *p_hidb, *p_hid2b;
    __nv_bfloat16 *p_wqpwb, *p_wprojb, *p_wmlp1b, *p_wmlp2b;
    cudaGetSymbolAddress((void**)&p_queryb, g_queryb);
    cudaGetSymbolAddress((void**)&p_out,   g_outb);
    cudaGetSymbolAddress((void**)&p_qdb,   g_qdb);
    cudaGetSymbolAddress((void**)&p_qqb,   g_qqb);
    cudaGetSymbolAddress((void**)&p_attb,  g_attb);
    cudaGetSymbolAddress((void**)&p_yb,    g_yb);
    cudaGetSymbolAddress((void**)&p_hidb,  g_hidb);
    cudaGetSymbolAddress((void**)&p_hid2b, g_hid2b);
    cudaGetSymbolAddress((void**)&p_wqpwb,  g_wqpwb);
    cudaGetSymbolAddress((void**)&p_wprojb, g_wprojb);
    cudaGetSymbolAddress((void**)&p_wmlp1b, g_wmlp1b);
    cudaGetSymbolAddress((void**)&p_wmlp2b, g_wmlp2b);

    cudaFuncSetAttribute(gemm_wmma<C,  true,  false>, cudaFuncAttributeMaxDynamicSharedMemorySize, GEMM_SMEM);
    cudaFuncSetAttribute(gemm_wmma<C,  false, true>,  cudaFuncAttributeMaxDynamicSharedMemorySize, GEMM_SMEM);
    cudaFuncSetAttribute(gemm_wmma<C4, false, true>,  cudaFuncAttributeMaxDynamicSharedMemorySize, GEMM_SMEM);

    // fused weight conversions (single launch)
    wconv_kernel<<<(2 * C * C + C4 * C + C * C4 + 255) / 256, 256>>>(w_q_pw, w_proj, w_mlp1, w_mlp2);

    // 1. LN + fuse
    ln_fuse_kernel<<<(B * HW + 255) / 256, 256>>>(low, high, gl, bl, gh, bh);
    // 2-3. mask path
    weff_kernel<<<NC, C>>>(w_ml2, w_ml1);
    int smem = (NC * C + C * 64) * (int)sizeof(float);
    cudaFuncSetAttribute(mask_xa_kernel, cudaFuncAttributeMaxDynamicSharedMemorySize, smem);
    mask_xa_kernel<<<dim3(HW / 256, B), 128, smem>>>(w_align);
    // 4-6. softmax, cf, kv
    softmax_hw_kernel<<<B * NC, 256>>>();
    cf_kernel<<<dim3(C / 8, B), 256>>>();
    kv_kernel<<<B * NC, 512>>>(w_kv, b_kv, memory);
    // 7. query depthwise (tiled), then q_pw GEMM (bf16 out)
    dw3x3t_kernel<__nv_bfloat16, __nv_bfloat16, false><<<dim3(B * C, H / 8), 256>>>(
        p_queryb, p_qdb, w_q_dw, b_q_dw, C);
    gemm_wmma<C, true, false><<<dim3(HW / 256, C / 128, B), 256, GEMM_SMEM>>>(
        p_wqpwb, p_qdb, p_qqb, b_q_pw, nullptr, C);
    // 8. attention
    attn_kernel<<<dim3(HW / 128, B), 256>>>();
    // 9. proj + residual(low)
    gemm_wmma<C, false, true><<<dim3(HW / 256, C / 128, B), 256, GEMM_SMEM>>>(
        p_wprojb, p_attb, p_out, b_proj, low, C);
    // 10. FFN
    ln_bf_kernel<<<(B * HW + 255) / 256, 256>>>(p_out, p_yb, gm, bm);
    gemm_wmma<C, true, false><<<dim3(HW / 256, C4 / 128, B), 256, GEMM_SMEM>>>(
        p_wmlp1b, p_yb, p_hidb, b_mlp1, nullptr, C4);
    dw3x3t_kernel<__nv_bfloat16, __nv_bfloat16, true><<<dim3(B * C4, H / 8), 256>>>(
        p_hidb, p_hid2b, w_mlpdw, b_mlpdw, C4);
    gemm_wmma<C4, false, true><<<dim3(HW / 256, C / 128, B), 256, GEMM_SMEM>>>(
        p_wmlp2b, p_hid2b, out, b_mlp2, p_out, C);
}

// round 15
// speedup vs baseline: 1.0174x; 1.0174x over previous
#include <cuda_runtime.h>
#include <cuda_bf16.h>
#include <mma.h>
#include <math.h>
#include <cstdint>

using namespace nvcuda;

// ---------------------------------------------------------------------------
// Problem constants
// ---------------------------------------------------------------------------
namespace {
constexpr int B  = 4;
constexpr int C  = 256;
constexpr int H  = 128;
constexpr int W  = 128;
constexpr int HW = H * W;          // 16384
constexpr int NC = 19;
constexpr int HD = 32;
constexpr int C4 = 4 * C;          // 1024
constexpr float SCALE = 0.17677669529663687f;
constexpr float EPS = 1e-5f;
}

// ---------------------------------------------------------------------------
// Scratch
// ---------------------------------------------------------------------------
__device__ __nv_bfloat16 g_queryb[B * C * HW];
__device__ __nv_bfloat16 g_fusedb[B * C * HW];
__device__ float g_mask [B * NC * HW];
__device__ __nv_bfloat16 g_xab [B * C * HW];
__device__ float g_weff [NC * C];
__device__ float g_cf   [B * NC * C];
__device__ float g_kbuf [B * NC * C];
__device__ float g_vbuf [B * NC * C];
__device__ float g_outb [B * C * HW];
__device__ __nv_bfloat16 g_qdb  [B * C * HW];
__device__ __nv_bfloat16 g_qqb  [B * C * HW];
__device__ __nv_bfloat16 g_attb [B * C * HW];
__device__ __nv_bfloat16 g_yb   [B * C * HW];
__device__ __nv_bfloat16 g_hidb [B * C4 * HW];
__device__ __nv_bfloat16 g_hid2b[B * C4 * HW];
__device__ __nv_bfloat16 g_wqpwb [C * C];
__device__ __nv_bfloat16 g_wprojb[C * C];
__device__ __nv_bfloat16 g_wmlp1b[C4 * C];
__device__ __nv_bfloat16 g_wmlp2b[C * C4];

// ---------------------------------------------------------------------------
// helpers
// ---------------------------------------------------------------------------
__device__ __forceinline__ uint32_t smem_u32(const void* p) {
    uint32_t a;
    asm("{ .reg .u64 t; cvta.to.shared.u64 t, %1; cvt.u32.u64 %0, t; }" : "=r"(a) : "l"(p));
    return a;
}
__device__ __forceinline__ void cp_async16(uint32_t saddr, const void* gaddr) {
    asm volatile("cp.async.cg.shared.global [%0], [%1], 16;" :: "r"(saddr), "l"(gaddr));
}
#define CP_COMMIT() asm volatile("cp.async.commit_group;" ::: "memory")
#define CP_WAIT(n)  asm volatile("cp.async.wait_group %0;" :: "n"(n) : "memory")

// ---------------------------------------------------------------------------
// Fused fp32 -> bf16 conversion for all four weight tensors (one launch)
// ---------------------------------------------------------------------------
__global__ void wconv_kernel(const float* __restrict__ w_q_pw, const float* __restrict__ w_proj,
                             const float* __restrict__ w_mlp1, const float* __restrict__ w_mlp2)
{
    int i = blockIdx.x * 256 + threadIdx.x;
    constexpr int N1 = C * C;
    constexpr int N2 = 2 * C * C;
    constexpr int N3 = N2 + C4 * C;
    constexpr int N4 = N3 + C * C4;
    if (i < N1)       g_wqpwb [i]      = __float2bfloat16(w_q_pw[i]);
    else if (i < N2)  g_wprojb[i - N1] = __float2bfloat16(w_proj[i - N1]);
    else if (i < N3)  g_wmlp1b[i - N2] = __float2bfloat16(w_mlp1[i - N2]);
    else if (i < N4)  g_wmlp2b[i - N3] = __float2bfloat16(w_mlp2[i - N3]);
}

// ---------------------------------------------------------------------------
// K1: LN(low) -> query(bf16) ; LN(high) ; fused(bf16) = 0.5*(q + ln_high)
// ---------------------------------------------------------------------------
__global__ void ln_fuse_kernel(const float* __restrict__ low, const float* __restrict__ high,
                               const float* __restrict__ gl, const float* __restrict__ bl,
                               const float* __restrict__ gh, const float* __restrict__ bh)
{
    int pos = blockIdx.x * blockDim.x + threadIdx.x;
    if (pos >= B * HW) return;
    int b = pos / HW, l = pos % HW;
    const float* lp = low  + (size_t)b * C * HW + l;
    const float* hp = high + (size_t)b * C * HW + l;
    float s1 = 0.f, s2 = 0.f, t1 = 0.f, t2 = 0.f;
    #pragma unroll 8
    for (int c = 0; c < C; c++) {
        float a = lp[(size_t)c * HW]; s1 += a; s2 += a * a;
        float e = hp[(size_t)c * HW]; t1 += e; t2 += e * e;
    }
    float mu1 = s1 * (1.f / C), mu2 = t1 * (1.f / C);
    float i1 = rsqrtf(s2 * (1.f / C) - mu1 * mu1 + EPS);
    float i2 = rsqrtf(t2 * (1.f / C) - mu2 * mu2 + EPS);
    __nv_bfloat16* qo = g_queryb + (size_t)b * C * HW + l;
    __nv_bfloat16* fo = g_fusedb + (size_t)b * C * HW + l;
    #pragma unroll 8
    for (int c = 0; c < C; c++) {
        float q = (lp[(size_t)c * HW] - mu1) * i1 * gl[c] + bl[c];
        float k = (hp[(size_t)c * HW] - mu2) * i2 * gh[c] + bh[c];
        qo[(size_t)c * HW] = __float2bfloat16(q);
        fo[(size_t)c * HW] = __float2bfloat16(0.5f * (q + k));
    }
}

// LN over channels -> bf16 out
__global__ void ln_bf_kernel(const float* __restrict__ in, __nv_bfloat16* __restrict__ out,
                             const float* __restrict__ g, const float* __restrict__ bb)
{
    int pos = blockIdx.x * blockDim.x + threadIdx.x;
    if (pos >= B * HW) return;
    int b = pos / HW, l = pos % HW;
    const float* ip = in + (size_t)b * C * HW + l;
    float s1 = 0.f, s2 = 0.f;
    #pragma unroll 8
    for (int c = 0; c < C; c++) { float a = ip[(size_t)c * HW]; s1 += a; s2 += a * a; }
    float mu = s1 * (1.f / C);
    float iv = rsqrtf(s2 * (1.f / C) - mu * mu + EPS);
    __nv_bfloat16* op = out + (size_t)b * C * HW + l;
    #pragma unroll 8
    for (int c = 0; c < C; c++)
        op[(size_t)c * HW] = __float2bfloat16((ip[(size_t)c * HW] - mu) * iv * g[c] + bb[c]);
}

// ---------------------------------------------------------------------------
// K2: compose mask-path weights
// ---------------------------------------------------------------------------
__global__ void weff_kernel(const float* __restrict__ w_ml2, const float* __restrict__ w_ml1)
{
    int n = blockIdx.x, ci = threadIdx.x;
    int g = ci >> 6, jj = ci & 63;
    float acc = 0.f;
    #pragma unroll
    for (int j = 0; j < 64; j++) {
        int m = g * 64 + j;
        acc += w_ml2[n * C + m] * w_ml1[m * 64 + jj];
    }
    g_weff[n * C + ci] = acc;
}

// ---------------------------------------------------------------------------
// K3a: grouped align conv, one group per block.z — 16 KB smem, high occupancy
// grid = (HW/256, B, 4), block 128, 2 positions/thread
// ---------------------------------------------------------------------------
__global__ __launch_bounds__(128) void xa_kernel(const float* __restrict__ w_align)
{
    __shared__ float wal_s[64 * 64];     // this group's [co][j] slice, 16 KB
    int tid = threadIdx.x;
    int g = blockIdx.z;
    for (int i = tid; i < 64 * 64; i += 128) wal_s[i] = w_align[g * 64 * 64 + i];
    __syncthreads();
    int b = blockIdx.y;
    int l0 = blockIdx.x * 256 + tid;
    int l1 = l0 + 128;
    const __nv_bfloat16* fb = g_fusedb + (size_t)b * C * HW + (size_t)(g * 64) * HW;
    float f0[64], f1[64];
    #pragma unroll
    for (int j = 0; j < 64; j++) {
        size_t co = (size_t)j * HW;
        f0[j] = __bfloat162float(fb[co + l0]);
        f1[j] = __bfloat162float(fb[co + l1]);
    }
    __nv_bfloat16* xo = g_xab + (size_t)b * C * HW + (size_t)(g * 64) * HW;
    for (int co = 0; co < 64; co++) {
        const float* wr = wal_s + co * 64;
        float a0 = 0.f, a1 = 0.f;
        #pragma unroll
        for (int j = 0; j < 64; j++) { float w = wr[j]; a0 += w * f0[j]; a1 += w * f1[j]; }
        size_t o = (size_t)co * HW;
        xo[o + l0] = __float2bfloat16(a0);
        xo[o + l1] = __float2bfloat16(a1);
    }
}

// ---------------------------------------------------------------------------
// K3b: mask logits — streaming channel loop, 19 KB smem
// grid = (HW/256, B), block 128, 2 positions/thread
// ---------------------------------------------------------------------------
__global__ __launch_bounds__(128) void mask_kernel()
{
    __shared__ float weff_s[NC * C];     // 19 KB
    int tid = threadIdx.x;
    for (int i = tid; i < NC * C; i += 128) weff_s[i] = g_weff[i];
    __syncthreads();
    int b = blockIdx.y;
    int l0 = blockIdx.x * 256 + tid;
    int l1 = l0 + 128;
    const __nv_bfloat16* fb = g_fusedb + (size_t)b * C * HW;
    float m0[NC], m1[NC];
    #pragma unroll
    for (int n = 0; n < NC; n++) { m0[n] = 0.f; m1[n] = 0.f; }
    #pragma unroll 4
    for (int c = 0; c < C; c++) {
        size_t co = (size_t)c * HW;
        float f0 = __bfloat162float(fb[co + l0]);
        float f1 = __bfloat162float(fb[co + l1]);
        #pragma unroll
        for (int n = 0; n < NC; n++) {
            float w = weff_s[n * C + c];
            m0[n] += w * f0; m1[n] += w * f1;
        }
    }
    #pragma unroll
    for (int n = 0; n < NC; n++) {
        size_t o = (size_t)b * NC * HW + (size_t)n * HW;
        g_mask[o + l0] = m0[n];
        g_mask[o + l1] = m1[n];
    }
}

// ---------------------------------------------------------------------------
// K4: spatial softmax over HW per (b,nc)
// ---------------------------------------------------------------------------
__global__ void softmax_hw_kernel()
{
    __shared__ float red[256];
    int row = blockIdx.x;
    float* p = g_mask + (size_t)row * HW;
    int tid = threadIdx.x;
    float m = -1e30f;
    for (int i = tid; i < HW; i += 256) m = fmaxf(m, p[i]);
    red[tid] = m; __syncthreads();
    for (int s = 128; s > 0; s >>= 1) { if (tid < s) red[tid] = fmaxf(red[tid], red[tid + s]); __syncthreads(); }
    m = red[0]; __syncthreads();
    float s = 0.f;
    for (int i = tid; i < HW; i += 256) s += expf(p[i] - m);
    red[tid] = s; __syncthreads();
    for (int st = 128; st > 0; st >>= 1) { if (tid < st) red[tid] += red[tid + st]; __syncthreads(); }
    float inv = 1.f / red[0];
    for (int i = tid; i < HW; i += 256) p[i] = expf(p[i] - m) * inv;
}

// ---------------------------------------------------------------------------
// K5: cf[b,n,c] — 8 channels per block
// ---------------------------------------------------------------------------
__global__ __launch_bounds__(256) void cf_kernel()
{
    int c0 = blockIdx.x * 8, b = blockIdx.y;
    int tid = threadIdx.x;
    const __nv_bfloat16* xp = g_xab + (size_t)(b * C + c0) * HW;
    const float* mp = g_mask + (size_t)b * NC * HW;
    float acc[NC][8];
    #pragma unroll
    for (int n = 0; n < NC; n++)
        #pragma unroll
        for (int cc = 0; cc < 8; cc++) acc[n][cc] = 0.f;
    for (int l = tid; l < HW; l += 256) {
        float xv[8];
        #pragma unroll
        for (int cc = 0; cc < 8; cc++) xv[cc] = __bfloat162float(xp[(size_t)cc * HW + l]);
        #pragma unroll
        for (int n = 0; n < NC; n++) {
            float m = mp[(size_t)n * HW + l];
            #pragma unroll
            for (int cc = 0; cc < 8; cc++) acc[n][cc] += m * xv[cc];
        }
    }
    __shared__ float red[8][NC * 8];
    int lane = tid & 31, wd = tid >> 5;
    #pragma unroll
    for (int n = 0; n < NC; n++)
        #pragma unroll
        for (int cc = 0; cc < 8; cc++) {
            float v = acc[n][cc];
            #pragma unroll
            for (int off = 16; off > 0; off >>= 1) v += __shfl_down_sync(0xFFFFFFFFu, v, off);
            if (lane == 0) red[wd][n * 8 + cc] = v;
        }
    __syncthreads();
    if (tid < NC * 8) {
        float s = 0.f;
        #pragma unroll
        for (int w = 0; w < 8; w++) s += red[w][tid];
        int n = tid >> 3, cc = tid & 7;
        g_cf[((size_t)b * NC + n) * C + c0 + cc] = s;
    }
}

// ---------------------------------------------------------------------------
// K6: memory-mix + kv projection
// ---------------------------------------------------------------------------
__global__ void kv_kernel(const float* __restrict__ w_kv, const float* __restrict__ b_kv,
                          const float* __restrict__ memory)
{
    int row = blockIdx.x;
    int n = row % NC;
    int tid = threadIdx.x;
    __shared__ float cfs[C];
    if (tid < C) cfs[tid] = 0.9f * g_cf[(size_t)row * C + tid] + 0.1f * memory[n * C + tid];
    __syncthreads();
    float acc = b_kv[tid];
    #pragma unroll 8
    for (int c = 0; c < C; c++) acc += cfs[c] * w_kv[(size_t)tid * C + c];
    if (tid < C) g_kbuf[(size_t)row * C + tid] = acc;
    else         g_vbuf[(size_t)row * C + tid - C] = acc;
}

// ---------------------------------------------------------------------------
// Depthwise 3x3 tiled
// ---------------------------------------------------------------------------
__device__ __forceinline__ float ldf(const float* p) { return *p; }
__device__ __forceinline__ float ldf(const __nv_bfloat16* p) { return __bfloat162float(*p); }

template <typename Tin, typename Tout, bool GELU>
__global__ __launch_bounds__(256) void dw3x3t_kernel(
    const Tin* __restrict__ in, Tout* __restrict__ out,
    const float* __restrict__ w, const float* __restrict__ bias, int Cn)
{
    __shared__ float tile[10][132];
    int bc = blockIdx.x;
    int y0 = blockIdx.y * 8;
    int c = bc % Cn;
    const Tin* ip = in + (size_t)bc * HW;
    int tid = threadIdx.x;
    #pragma unroll
    for (int i = tid; i < 10 * 132; i += 256) {
        int ry = i / 132, rx = i % 132;
        int gy = y0 - 1 + ry, gx = rx - 1;
        float v = 0.f;
        if (gy >= 0 && gy < H && gx >= 0 && gx < W) v = ldf(ip + gy * W + gx);
        tile[ry][rx] = v;
    }
    __syncthreads();
    float w0 = w[c*9+0], w1 = w[c*9+1], w2 = w[c*9+2];
    float w3 = w[c*9+3], w4 = w[c*9+4], w5 = w[c*9+5];
    float w6 = w[c*9+6], w7 = w[c*9+7], w8 = w[c*9+8];
    float bv = bias[c];
    int tx = tid & 31, ty = tid >> 5;
    int xb = tx * 4;
    float acc[4] = { bv, bv, bv, bv };
    {
        const float* r0 = tile[ty + 0];
        const float* r1 = tile[ty + 1];
        const float* r2 = tile[ty + 2];
        float v0[6], v1[6], v2[6];
        #pragma unroll
        for (int j = 0; j < 6; j++) { v0[j] = r0[xb+j]; v1[j] = r1[xb+j]; v2[j] = r2[xb+j]; }
        #pragma unroll
        for (int o = 0; o < 4; o++) {
            acc[o] += v0[o]*w0 + v0[o+1]*w1 + v0[o+2]*w2;
            acc[o] += v1[o]*w3 + v1[o+1]*w4 + v1[o+2]*w5;
            acc[o] += v2[o]*w6 + v2[o+1]*w7 + v2[o+2]*w8;
        }
    }
    if (GELU) {
        #pragma unroll
        for (int o = 0; o < 4; o++) {
            float x = acc[o];
            float u = 1.5957691216057308f * (x + 0.044715f * x * x * x);
            float s = 1.f / (1.f + __expf(-u));
            acc[o] = x * s;
        }
    }
    size_t obase = (size_t)bc * HW + (size_t)(y0 + ty) * W + xb;
    if (sizeof(Tout) == 2) {
        __nv_bfloat162 h0 = __floats2bfloat162_rn(acc[0], acc[1]);
        __nv_bfloat162 h1 = __floats2bfloat162_rn(acc[2], acc[3]);
        uint2 pk = { *(uint32_t*)&h0, *(uint32_t*)&h1 };
        *(uint2*)((__nv_bfloat16*)out + obase) = pk;
    } else {
        float4 v = { acc[0], acc[1], acc[2], acc[3] };
        *(float4*)((float*)out + obase) = v;
    }
}

// ---------------------------------------------------------------------------
// Attention v2: 4 positions/thread, vectorized q loads/stores
// ---------------------------------------------------------------------------
__global__ __launch_bounds__(256) void attn_kernel()
{
    __shared__ float ks[NC * C], vs[NC * C];
    int b = blockIdx.y;
    int tid = threadIdx.x;
    for (int i = tid; i < NC * C; i += 256) {
        ks[i] = g_kbuf[(size_t)b * NC * C + i];
        vs[i] = g_vbuf[(size_t)b * NC * C + i];
    }
    __syncthreads();
    int h = tid >> 5, lane = tid & 31;
    int l0 = blockIdx.x * 128 + lane * 4;
    const __nv_bfloat16* qp = g_qqb + (size_t)b * C * HW + (size_t)(h * HD) * HW + l0;
    float a[4][NC];
    #pragma unroll
    for (int p = 0; p < 4; p++)
        #pragma unroll
        for (int n = 0; n < NC; n++) a[p][n] = 0.f;
    #pragma unroll
    for (int d = 0; d < HD; d++) {
        uint2 pk = *(const uint2*)(qp + (size_t)d * HW);
        __nv_bfloat162 q01 = *(__nv_bfloat162*)&pk.x;
        __nv_bfloat162 q23 = *(__nv_bfloat162*)&pk.y;
        float qv[4] = { __bfloat162float(q01.x), __bfloat162float(q01.y),
                        __bfloat162float(q23.x), __bfloat162float(q23.y) };
        const float* kd = ks + h * HD + d;
        #pragma unroll
        for (int n = 0; n < NC; n++) {
            float kv = kd[n * C];
            #pragma unroll
            for (int p = 0; p < 4; p++) a[p][n] += qv[p] * kv;
        }
    }
    float inv[4];
    #pragma unroll
    for (int p = 0; p < 4; p++) {
        float mn = 1e30f;
        #pragma unroll
        for (int n = 0; n < NC; n++) { a[p][n] *= SCALE; mn = fminf(mn, a[p][n]); }
        float s = 0.f;
        #pragma unroll
        for (int n = 0; n < NC; n++) { a[p][n] = expf(mn - a[p][n]); s += a[p][n]; }
        inv[p] = 1.f / s;
    }
    __nv_bfloat16* op = g_attb + (size_t)b * C * HW + (size_t)(h * HD) * HW + l0;
    #pragma unroll
    for (int d = 0; d < HD; d++) {
        const float* vd = vs + h * HD + d;
        float acc[4] = { 0.f, 0.f, 0.f, 0.f };
        #pragma unroll
        for (int n = 0; n < NC; n++) {
            float vv = vd[n * C];
            #pragma unroll
            for (int p = 0; p < 4; p++) acc[p] += a[p][n] * vv;
        }
        __nv_bfloat162 h0 = __floats2bfloat162_rn(acc[0] * inv[0], acc[1] * inv[1]);
        __nv_bfloat162 h1 = __floats2bfloat162_rn(acc[2] * inv[2], acc[3] * inv[3]);
        uint2 pk = { *(uint32_t*)&h0, *(uint32_t*)&h1 };
        *(uint2*)(op + (size_t)d * HW) = pk;
    }
}

// ---------------------------------------------------------------------------
// WMMA bf16 GEMM (R13 config, runtime K): Y = W @ X (+bias)(+res)
// ---------------------------------------------------------------------------
constexpr int LDA = 40;
constexpr int LDB = 264;
constexpr int A_BUF = 128 * LDA;
constexpr int B_BUF = 32 * LDB;
constexpr int GEMM_SMEM = (2 * A_BUF + 2 * B_BUF) * 2;

template <bool OUT_BF16, bool HAS_RES>
__global__ __launch_bounds__(256) void gemm_wmma(
    const __nv_bfloat16* __restrict__ Wb, const __nv_bfloat16* __restrict__ X,
    void* __restrict__ Y, const float* __restrict__ bias, const float* __restrict__ res,
    int M, int K)
{
    extern __shared__ char smem[];
    __nv_bfloat16* As = (__nv_bfloat16*)smem;
    __nv_bfloat16* Bs = As + 2 * A_BUF;
    uint32_t a_base = smem_u32(As);
    uint32_t b_base = smem_u32(Bs);

    int tid = threadIdx.x;
    int wid = tid >> 5;
    int wm = wid & 1;
    int wn = wid >> 1;
    int n0 = blockIdx.x * 256;
    int bm = blockIdx.y;
    int b  = blockIdx.z;

    const __nv_bfloat16* Ag = Wb + (size_t)(bm * 128) * K;
    const __nv_bfloat16* Xg = X + (size_t)b * K * HW + n0;

    wmma::fragment<wmma::accumulator, 16, 16, 16, float> acc[4][4];
    #pragma unroll
    for (int i = 0; i < 4; i++)
        #pragma unroll
        for (int j = 0; j < 4; j++) wmma::fill_fragment(acc[i][j], 0.f);

    int nk = K >> 5;

    auto load_tile = [&](int kt, int buf) {
        int k0 = kt * 32;
        #pragma unroll
        for (int i = 0; i < 2; i++) {
            int cid = i * 256 + tid;
            int r = cid >> 2, c8 = (cid & 3) * 8;
            cp_async16(a_base + (buf * A_BUF + r * LDA + c8) * 2,
                       Ag + (size_t)r * K + k0 + c8);
        }
        #pragma unroll
        for (int i = 0; i < 4; i++) {
            int cid = i * 256 + tid;
            int r = cid >> 5, c8 = (cid & 31) * 8;
            cp_async16(b_base + (buf * B_BUF + r * LDB + c8) * 2,
                       Xg + (size_t)(k0 + r) * HW + c8);
        }
        CP_COMMIT();
    };

    load_tile(0, 0);

    for (int kt = 0; kt < nk; kt++) {
        int buf = kt & 1;
        if (kt + 1 < nk) { load_tile(kt + 1, buf ^ 1); CP_WAIT(1); }
        else             { CP_WAIT(0); }
        __syncthreads();
        const __nv_bfloat16* Ab = As + buf * A_BUF;
        const __nv_bfloat16* Bb = Bs + buf * B_BUF;
        #pragma unroll
        for (int kk = 0; kk < 2; kk++) {
            wmma::fragment<wmma::matrix_a, 16, 16, 16, __nv_bfloat16, wmma::row_major> af[4];
            #pragma unroll
            for (int i = 0; i < 4; i++)
                wmma::load_matrix_sync(af[i], Ab + (wm * 64 + i * 16) * LDA + kk * 16, LDA);
            #pragma unroll
            for (int j = 0; j < 4; j++) {
                wmma::fragment<wmma::matrix_b, 16, 16, 16, __nv_bfloat16, wmma::row_major> bf;
                wmma::load_matrix_sync(bf, Bb + (kk * 16) * LDB + wn * 64 + j * 16, LDB);
                #pragma unroll
                for (int i = 0; i < 4; i++)
                    wmma::mma_sync(acc[i][j], af[i], bf, acc[i][j]);
            }
        }
        __syncthreads();
    }

    float* stage_w = (float*)smem + wid * (16 * 20);
    int lane = tid & 31;
    int rbase = bm * 128 + wm * 64;
    int cbase = n0 + wn * 64;
    size_t bb0 = (size_t)b * M * HW;
    int r = lane >> 1, cp4 = (lane & 1) * 8;
    #pragma unroll
    for (int i = 0; i < 4; i++) {
        #pragma unroll
        for (int j = 0; j < 4; j++) {
            wmma::store_matrix_sync(stage_w, acc[i][j], 20, wmma::mem_row_major);
            __syncwarp();
            int row = rbase + i * 16 + r;
            float bv = bias[row];
            size_t o = bb0 + (size_t)row * HW + cbase + j * 16 + cp4;
            float4 v0 = *(float4*)(stage_w + r * 20 + cp4);
            float4 v1 = *(float4*)(stage_w + r * 20 + cp4 + 4);
            v0.x += bv; v0.y += bv; v0.z += bv; v0.w += bv;
            v1.x += bv; v1.y += bv; v1.z += bv; v1.w += bv;
            if (HAS_RES) {
                float4 r0 = *(const float4*)(res + o);
                float4 r1 = *(const float4*)(res + o + 4);
                v0.x += r0.x; v0.y += r0.y; v0.z += r0.z; v0.w += r0.w;
                v1.x += r1.x; v1.y += r1.y; v1.z += r1.z; v1.w += r1.w;
            }
            if (OUT_BF16) {
                __nv_bfloat162 h0 = __floats2bfloat162_rn(v0.x, v0.y);
                __nv_bfloat162 h1 = __floats2bfloat162_rn(v0.z, v0.w);
                __nv_bfloat162 h2 = __floats2bfloat162_rn(v1.x, v1.y);
                __nv_bfloat162 h3 = __floats2bfloat162_rn(v1.z, v1.w);
                uint4 pk = { *(uint32_t*)&h0, *(uint32_t*)&h1, *(uint32_t*)&h2, *(uint32_t*)&h3 };
                *(uint4*)((__nv_bfloat16*)Y + o) = pk;
            } else {
                *(float4*)((float*)Y + o) = v0;
                *(float4*)((float*)Y + o + 4) = v1;
            }
            __syncwarp();
        }
    }
}

// ---------------------------------------------------------------------------
// Host launcher
// ---------------------------------------------------------------------------
extern "C" void kernel_launch(void* const* d_in, const int* in_sizes, int n_in,
                              void* d_out, int out_size)
{
    const float* low     = (const float*)d_in[0];
    const float* high    = (const float*)d_in[1];
    const float* gl      = (const float*)d_in[2];
    const float* bl      = (const float*)d_in[3];
    const float* gh      = (const float*)d_in[4];
    const float* bh      = (const float*)d_in[5];
    const float* gm      = (const float*)d_in[6];
    const float* bm      = (const float*)d_in[7];
    const float* w_q_dw  = (const float*)d_in[8];
    const float* b_q_dw  = (const float*)d_in[9];
    const float* w_q_pw  = (const float*)d_in[10];
    const float* b_q_pw  = (const float*)d_in[11];
    const float* w_ml1   = (const float*)d_in[12];
    const float* w_ml2   = (const float*)d_in[13];
    const float* w_align = (const float*)d_in[14];
    const float* w_kv    = (const float*)d_in[15];
    const float* b_kv    = (const float*)d_in[16];
    const float* memory  = (const float*)d_in[17];
    const float* w_proj  = (const float*)d_in[18];
    const float* b_proj  = (const float*)d_in[19];
    const float* w_mlp1  = (const float*)d_in[20];
    const float* b_mlp1  = (const float*)d_in[21];
    const float* w_mlpdw = (const float*)d_in[22];
    const float* b_mlpdw = (const float*)d_in[23];
    const float* w_mlp2  = (const float*)d_in[24];
    const float* b_mlp2  = (const float*)d_in[25];
    float* out = (float*)d_out;

    float *p_out;
    __nv_bfloat16 *p_queryb, *p_qdb, *p_qqb, *p_attb, *p_yb, *p_hidb, *p_hid2b;
    __nv_bfloat16 *p_wqpwb, *p_wprojb, *p_wmlp1b, *p_wmlp2b;
    cudaGetSymbolAddress((void**)&p_queryb, g_queryb);
    cudaGetSymbolAddress((void**)&p_out,   g_outb);
    cudaGetSymbolAddress((void**)&p_qdb,   g_qdb);
    cudaGetSymbolAddress((void**)&p_qqb,   g_qqb);
    cudaGetSymbolAddress((void**)&p_attb,  g_attb);
    cudaGetSymbolAddress((void**)&p_yb,    g_yb);
    cudaGetSymbolAddress((void**)&p_hidb,  g_hidb);
    cudaGetSymbolAddress((void**)&p_hid2b, g_hid2b);
    cudaGetSymbolAddress((void**)&p_wqpwb,  g_wqpwb);
    cudaGetSymbolAddress((void**)&p_wprojb, g_wprojb);
    cudaGetSymbolAddress((void**)&p_wmlp1b, g_wmlp1b);
    cudaGetSymbolAddress((void**)&p_wmlp2b, g_wmlp2b);

    cudaFuncSetAttribute(gemm_wmma<true,  false>, cudaFuncAttributeMaxDynamicSharedMemorySize, GEMM_SMEM);
    cudaFuncSetAttribute(gemm_wmma<false, true>,  cudaFuncAttributeMaxDynamicSharedMemorySize, GEMM_SMEM);

    // fused weight conversions (single launch)
    wconv_kernel<<<(2 * C * C + C4 * C + C * C4 + 255) / 256, 256>>>(w_q_pw, w_proj, w_mlp1, w_mlp2);

    // 1. LN + fuse
    ln_fuse_kernel<<<(B * HW + 255) / 256, 256>>>(low, high, gl, bl, gh, bh);
    // 2-3. mask path (split kernels for occupancy)
    weff_kernel<<<NC, C>>>(w_ml2, w_ml1);
    xa_kernel<<<dim3(HW / 256, B, 4), 128>>>(w_align);
    mask_kernel<<<dim3(HW / 256, B), 128>>>();
    // 4-6. softmax, cf, kv
    softmax_hw_kernel<<<B * NC, 256>>>();
    cf_kernel<<<dim3(C / 8, B), 256>>>();
    kv_kernel<<<B * NC, 512>>>(w_kv, b_kv, memory);
    // 7. query depthwise (tiled), then q_pw GEMM (bf16 out)
    dw3x3t_kernel<__nv_bfloat16, __nv_bfloat16, false><<<dim3(B * C, H / 8), 256>>>(
        p_queryb, p_qdb, w_q_dw, b_q_dw, C);
    gemm_wmma<true, false><<<dim3(HW / 256, C / 128, B), 256, GEMM_SMEM>>>(
        p_wqpwb, p_qdb, p_qqb, b_q_pw, nullptr, C, C);
    // 8. attention
    attn_kernel<<<dim3(HW / 128, B), 256>>>();
    // 9. proj + residual(low)
    gemm_wmma<false, true><<<dim3(HW / 256, C / 128, B), 256, GEMM_SMEM>>>(
        p_wprojb, p_attb, p_out, b_proj, low, C, C);
    // 10. FFN
    ln_bf_kernel<<<(B * HW + 255) / 256, 256>>>(p_out, p_yb, gm, bm);
    gemm_wmma<true, false><<<dim3(HW / 256, C4 / 128, B), 256, GEMM_SMEM>>>(
        p_wmlp1b, p_yb, p_hidb, b_mlp1, nullptr, C4, C);
    dw3x3t_kernel<__nv_bfloat16, __nv_bfloat16, true><<<dim3(B * C4, H / 8), 256>>>(
        p_hidb, p_hid2b, w_mlpdw, b_mlpdw, C4);
    gemm_wmma<false, true><<<dim3(HW / 256, C / 128, B), 256, GEMM_SMEM>>>(
        p_wmlp2b, p_hid2b, out, b_mlp2, p_out, C, C4);
}

// round 16
// speedup vs baseline: 1.0626x; 1.0443x over previous
#include <cuda_runtime.h>
#include <cuda_bf16.h>
#include <mma.h>
#include <math.h>
#include <cstdint>

using namespace nvcuda;

// ---------------------------------------------------------------------------
// Problem constants
// ---------------------------------------------------------------------------
namespace {
constexpr int B  = 4;
constexpr int C  = 256;
constexpr int H  = 128;
constexpr int W  = 128;
constexpr int HW = H * W;          // 16384
constexpr int NC = 19;
constexpr int HD = 32;
constexpr int C4 = 4 * C;          // 1024
constexpr float SCALE = 0.17677669529663687f;
constexpr float EPS = 1e-5f;
}

// ---------------------------------------------------------------------------
// Scratch
// ---------------------------------------------------------------------------
__device__ __nv_bfloat16 g_queryb[B * C * HW];
__device__ __nv_bfloat16 g_fusedb[B * C * HW];
__device__ float g_mask [B * NC * HW];
__device__ __nv_bfloat16 g_xab [B * C * HW];
__device__ float g_weff [NC * C];
__device__ float g_cf   [B * NC * C];
__device__ float g_kbuf [B * NC * C];
__device__ float g_vbuf [B * NC * C];
__device__ float g_outb [B * C * HW];
__device__ __nv_bfloat16 g_qdb  [B * C * HW];
__device__ __nv_bfloat16 g_qqb  [B * C * HW];
__device__ __nv_bfloat16 g_attb [B * C * HW];
__device__ __nv_bfloat16 g_yb   [B * C * HW];
__device__ __nv_bfloat16 g_hidb [B * C4 * HW];
__device__ __nv_bfloat16 g_hid2b[B * C4 * HW];
__device__ __nv_bfloat16 g_wqpwb [C * C];
__device__ __nv_bfloat16 g_wprojb[C * C];
__device__ __nv_bfloat16 g_wmlp1b[C4 * C];
__device__ __nv_bfloat16 g_wmlp2b[C * C4];

// ---------------------------------------------------------------------------
// helpers
// ---------------------------------------------------------------------------
__device__ __forceinline__ uint32_t smem_u32(const void* p) {
    uint32_t a;
    asm("{ .reg .u64 t; cvta.to.shared.u64 t, %1; cvt.u32.u64 %0, t; }" : "=r"(a) : "l"(p));
    return a;
}
__device__ __forceinline__ void cp_async16(uint32_t saddr, const void* gaddr) {
    asm volatile("cp.async.cg.shared.global [%0], [%1], 16;" :: "r"(saddr), "l"(gaddr));
}
#define CP_COMMIT() asm volatile("cp.async.commit_group;" ::: "memory")
#define CP_WAIT(n)  asm volatile("cp.async.wait_group %0;" :: "n"(n) : "memory")

// ---------------------------------------------------------------------------
// Fused fp32 -> bf16 conversion for all four weight tensors (one launch)
// ---------------------------------------------------------------------------
__global__ void wconv_kernel(const float* __restrict__ w_q_pw, const float* __restrict__ w_proj,
                             const float* __restrict__ w_mlp1, const float* __restrict__ w_mlp2)
{
    int i = blockIdx.x * 256 + threadIdx.x;
    constexpr int N1 = C * C;
    constexpr int N2 = 2 * C * C;
    constexpr int N3 = N2 + C4 * C;
    constexpr int N4 = N3 + C * C4;
    if (i < N1)       g_wqpwb [i]      = __float2bfloat16(w_q_pw[i]);
    else if (i < N2)  g_wprojb[i - N1] = __float2bfloat16(w_proj[i - N1]);
    else if (i < N3)  g_wmlp1b[i - N2] = __float2bfloat16(w_mlp1[i - N2]);
    else if (i < N4)  g_wmlp2b[i - N3] = __float2bfloat16(w_mlp2[i - N3]);
}

// ---------------------------------------------------------------------------
// K1: LN(low) -> query(bf16) ; LN(high) ; fused(bf16) = 0.5*(q + ln_high)
// ---------------------------------------------------------------------------
__global__ void ln_fuse_kernel(const float* __restrict__ low, const float* __restrict__ high,
                               const float* __restrict__ gl, const float* __restrict__ bl,
                               const float* __restrict__ gh, const float* __restrict__ bh)
{
    int pos = blockIdx.x * blockDim.x + threadIdx.x;
    if (pos >= B * HW) return;
    int b = pos / HW, l = pos % HW;
    const float* lp = low  + (size_t)b * C * HW + l;
    const float* hp = high + (size_t)b * C * HW + l;
    float s1 = 0.f, s2 = 0.f, t1 = 0.f, t2 = 0.f;
    #pragma unroll 8
    for (int c = 0; c < C; c++) {
        float a = lp[(size_t)c * HW]; s1 += a; s2 += a * a;
        float e = hp[(size_t)c * HW]; t1 += e; t2 += e * e;
    }
    float mu1 = s1 * (1.f / C), mu2 = t1 * (1.f / C);
    float i1 = rsqrtf(s2 * (1.f / C) - mu1 * mu1 + EPS);
    float i2 = rsqrtf(t2 * (1.f / C) - mu2 * mu2 + EPS);
    __nv_bfloat16* qo = g_queryb + (size_t)b * C * HW + l;
    __nv_bfloat16* fo = g_fusedb + (size_t)b * C * HW + l;
    #pragma unroll 8
    for (int c = 0; c < C; c++) {
        float q = (lp[(size_t)c * HW] - mu1) * i1 * gl[c] + bl[c];
        float k = (hp[(size_t)c * HW] - mu2) * i2 * gh[c] + bh[c];
        qo[(size_t)c * HW] = __float2bfloat16(q);
        fo[(size_t)c * HW] = __float2bfloat16(0.5f * (q + k));
    }
}

// LN over channels -> bf16 out
__global__ void ln_bf_kernel(const float* __restrict__ in, __nv_bfloat16* __restrict__ out,
                             const float* __restrict__ g, const float* __restrict__ bb)
{
    int pos = blockIdx.x * blockDim.x + threadIdx.x;
    if (pos >= B * HW) return;
    int b = pos / HW, l = pos % HW;
    const float* ip = in + (size_t)b * C * HW + l;
    float s1 = 0.f, s2 = 0.f;
    #pragma unroll 8
    for (int c = 0; c < C; c++) { float a = ip[(size_t)c * HW]; s1 += a; s2 += a * a; }
    float mu = s1 * (1.f / C);
    float iv = rsqrtf(s2 * (1.f / C) - mu * mu + EPS);
    __nv_bfloat16* op = out + (size_t)b * C * HW + l;
    #pragma unroll 8
    for (int c = 0; c < C; c++)
        op[(size_t)c * HW] = __float2bfloat16((ip[(size_t)c * HW] - mu) * iv * g[c] + bb[c]);
}

// ---------------------------------------------------------------------------
// K2: compose mask-path weights
// ---------------------------------------------------------------------------
__global__ void weff_kernel(const float* __restrict__ w_ml2, const float* __restrict__ w_ml1)
{
    int n = blockIdx.x, ci = threadIdx.x;
    int g = ci >> 6, jj = ci & 63;
    float acc = 0.f;
    #pragma unroll
    for (int j = 0; j < 64; j++) {
        int m = g * 64 + j;
        acc += w_ml2[n * C + m] * w_ml1[m * 64 + jj];
    }
    g_weff[n * C + ci] = acc;
}

// ---------------------------------------------------------------------------
// K3 (R13-proven): mask logits + grouped align conv — 2 positions per thread
// ---------------------------------------------------------------------------
__global__ __launch_bounds__(128) void mask_xa_kernel(const float* __restrict__ w_align)
{
    extern __shared__ float sm[];
    float* weff_s = sm;
    float* wal_s  = sm + NC * C;
    int tid = threadIdx.x;
    for (int i = tid; i < NC * C; i += 128) weff_s[i] = g_weff[i];
    for (int i = tid; i < C * 64; i += 128) wal_s[i] = w_align[i];
    __syncthreads();
    int b = blockIdx.y;
    int l0 = blockIdx.x * 256 + tid;
    int l1 = l0 + 128;
    const __nv_bfloat16* fb = g_fusedb + (size_t)b * C * HW;
    float m0[NC], m1[NC];
    #pragma unroll
    for (int n = 0; n < NC; n++) { m0[n] = 0.f; m1[n] = 0.f; }
    for (int g = 0; g < 4; g++) {
        float f0[64], f1[64];
        #pragma unroll
        for (int j = 0; j < 64; j++) {
            size_t co = (size_t)(g * 64 + j) * HW;
            f0[j] = __bfloat162float(fb[co + l0]);
            f1[j] = __bfloat162float(fb[co + l1]);
        }
        for (int n = 0; n < NC; n++) {
            const float* wr = weff_s + n * C + g * 64;
            float a0 = 0.f, a1 = 0.f;
            #pragma unroll
            for (int j = 0; j < 64; j++) { float w = wr[j]; a0 += w * f0[j]; a1 += w * f1[j]; }
            m0[n] += a0; m1[n] += a1;
        }
        for (int co = 0; co < 64; co++) {
            const float* wr = wal_s + (g * 64 + co) * 64;
            float a0 = 0.f, a1 = 0.f;
            #pragma unroll
            for (int j = 0; j < 64; j++) { float w = wr[j]; a0 += w * f0[j]; a1 += w * f1[j]; }
            size_t o = (size_t)b * C * HW + (size_t)(g * 64 + co) * HW;
            g_xab[o + l0] = __float2bfloat16(a0);
            g_xab[o + l1] = __float2bfloat16(a1);
        }
    }
    #pragma unroll
    for (int n = 0; n < NC; n++) {
        size_t o = (size_t)b * NC * HW + (size_t)n * HW;
        g_mask[o + l0] = m0[n];
        g_mask[o + l1] = m1[n];
    }
}

// ---------------------------------------------------------------------------
// K4: spatial softmax over HW per (b,nc)
// ---------------------------------------------------------------------------
__global__ void softmax_hw_kernel()
{
    __shared__ float red[256];
    int row = blockIdx.x;
    float* p = g_mask + (size_t)row * HW;
    int tid = threadIdx.x;
    float m = -1e30f;
    for (int i = tid; i < HW; i += 256) m = fmaxf(m, p[i]);
    red[tid] = m; __syncthreads();
    for (int s = 128; s > 0; s >>= 1) { if (tid < s) red[tid] = fmaxf(red[tid], red[tid + s]); __syncthreads(); }
    m = red[0]; __syncthreads();
    float s = 0.f;
    for (int i = tid; i < HW; i += 256) s += expf(p[i] - m);
    red[tid] = s; __syncthreads();
    for (int st = 128; st > 0; st >>= 1) { if (tid < st) red[tid] += red[tid + st]; __syncthreads(); }
    float inv = 1.f / red[0];
    for (int i = tid; i < HW; i += 256) p[i] = expf(p[i] - m) * inv;
}

// ---------------------------------------------------------------------------
// K5: cf[b,n,c] — 8 channels per block
// ---------------------------------------------------------------------------
__global__ __launch_bounds__(256) void cf_kernel()
{
    int c0 = blockIdx.x * 8, b = blockIdx.y;
    int tid = threadIdx.x;
    const __nv_bfloat16* xp = g_xab + (size_t)(b * C + c0) * HW;
    const float* mp = g_mask + (size_t)b * NC * HW;
    float acc[NC][8];
    #pragma unroll
    for (int n = 0; n < NC; n++)
        #pragma unroll
        for (int cc = 0; cc < 8; cc++) acc[n][cc] = 0.f;
    for (int l = tid; l < HW; l += 256) {
        float xv[8];
        #pragma unroll
        for (int cc = 0; cc < 8; cc++) xv[cc] = __bfloat162float(xp[(size_t)cc * HW + l]);
        #pragma unroll
        for (int n = 0; n < NC; n++) {
            float m = mp[(size_t)n * HW + l];
            #pragma unroll
            for (int cc = 0; cc < 8; cc++) acc[n][cc] += m * xv[cc];
        }
    }
    __shared__ float red[8][NC * 8];
    int lane = tid & 31, wd = tid >> 5;
    #pragma unroll
    for (int n = 0; n < NC; n++)
        #pragma unroll
        for (int cc = 0; cc < 8; cc++) {
            float v = acc[n][cc];
            #pragma unroll
            for (int off = 16; off > 0; off >>= 1) v += __shfl_down_sync(0xFFFFFFFFu, v, off);
            if (lane == 0) red[wd][n * 8 + cc] = v;
        }
    __syncthreads();
    if (tid < NC * 8) {
        float s = 0.f;
        #pragma unroll
        for (int w = 0; w < 8; w++) s += red[w][tid];
        int n = tid >> 3, cc = tid & 7;
        g_cf[((size_t)b * NC + n) * C + c0 + cc] = s;
    }
}

// ---------------------------------------------------------------------------
// K6: memory-mix + kv projection
// ---------------------------------------------------------------------------
__global__ void kv_kernel(const float* __restrict__ w_kv, const float* __restrict__ b_kv,
                          const float* __restrict__ memory)
{
    int row = blockIdx.x;
    int n = row % NC;
    int tid = threadIdx.x;
    __shared__ float cfs[C];
    if (tid < C) cfs[tid] = 0.9f * g_cf[(size_t)row * C + tid] + 0.1f * memory[n * C + tid];
    __syncthreads();
    float acc = b_kv[tid];
    #pragma unroll 8
    for (int c = 0; c < C; c++) acc += cfs[c] * w_kv[(size_t)tid * C + c];
    if (tid < C) g_kbuf[(size_t)row * C + tid] = acc;
    else         g_vbuf[(size_t)row * C + tid - C] = acc;
}

// ---------------------------------------------------------------------------
// Depthwise 3x3 tiled, v2: vectorized interior loads (uint4 = 8 bf16/LDG)
// Block = 8 rows x 128 cols of one (b,c) plane. grid = (B*Cn, H/8), 256 thr.
// tile[ry][rx] holds value at gx = rx-1 (rx 0 and 129..131 are zero halo).
// ---------------------------------------------------------------------------
template <bool GELU>
__global__ __launch_bounds__(256) void dw3x3t_kernel(
    const __nv_bfloat16* __restrict__ in, __nv_bfloat16* __restrict__ out,
    const float* __restrict__ w, const float* __restrict__ bias, int Cn)
{
    __shared__ float tile[10][132];
    int bc = blockIdx.x;
    int y0 = blockIdx.y * 8;
    int c = bc % Cn;
    const __nv_bfloat16* ip = in + (size_t)bc * HW;
    int tid = threadIdx.x;

    if (tid < 160) {                       // interior: 10 rows x 16 chunks of 8
        int ry = tid / 16, cx = (tid % 16) * 8;
        int gy = y0 - 1 + ry;
        float v[8] = { 0.f, 0.f, 0.f, 0.f, 0.f, 0.f, 0.f, 0.f };
        if (gy >= 0 && gy < H) {
            uint4 pk = *(const uint4*)(ip + gy * W + cx);
            const __nv_bfloat162* h2 = (const __nv_bfloat162*)&pk;
            #pragma unroll
            for (int t = 0; t < 4; t++) {
                float2 f = __bfloat1622float2(h2[t]);
                v[2 * t] = f.x; v[2 * t + 1] = f.y;
            }
        }
        #pragma unroll
        for (int k = 0; k < 8; k++) tile[ry][1 + cx + k] = v[k];
    } else if (tid < 200) {                // halo: 10 rows x 4 cols {0,129,130,131}
        int e = tid - 160;
        int ry = e / 4, es = e % 4;
        int rx = (es == 0) ? 0 : (129 + es - 1);
        tile[ry][rx] = 0.f;
    }
    __syncthreads();

    float w0 = w[c*9+0], w1 = w[c*9+1], w2 = w[c*9+2];
    float w3 = w[c*9+3], w4 = w[c*9+4], w5 = w[c*9+5];
    float w6 = w[c*9+6], w7 = w[c*9+7], w8 = w[c*9+8];
    float bv = bias[c];
    int tx = tid & 31, ty = tid >> 5;
    int xb = tx * 4;
    float acc[4] = { bv, bv, bv, bv };
    {
        const float* r0 = tile[ty + 0];
        const float* r1 = tile[ty + 1];
        const float* r2 = tile[ty + 2];
        float v0[6], v1[6], v2[6];
        #pragma unroll
        for (int j = 0; j < 6; j++) { v0[j] = r0[xb+j]; v1[j] = r1[xb+j]; v2[j] = r2[xb+j]; }
        #pragma unroll
        for (int o = 0; o < 4; o++) {
            acc[o] += v0[o]*w0 + v0[o+1]*w1 + v0[o+2]*w2;
            acc[o] += v1[o]*w3 + v1[o+1]*w4 + v1[o+2]*w5;
            acc[o] += v2[o]*w6 + v2[o+1]*w7 + v2[o+2]*w8;
        }
    }
    if (GELU) {
        #pragma unroll
        for (int o = 0; o < 4; o++) {
            float x = acc[o];
            float u = 1.5957691216057308f * (x + 0.044715f * x * x * x);
            float s = 1.f / (1.f + __expf(-u));
            acc[o] = x * s;
        }
    }
    size_t obase = (size_t)bc * HW + (size_t)(y0 + ty) * W + xb;
    __nv_bfloat162 h0 = __floats2bfloat162_rn(acc[0], acc[1]);
    __nv_bfloat162 h1 = __floats2bfloat162_rn(acc[2], acc[3]);
    uint2 pk = { *(uint32_t*)&h0, *(uint32_t*)&h1 };
    *(uint2*)(out + obase) = pk;
}

// ---------------------------------------------------------------------------
// Attention: 4 positions/thread, vectorized q loads/stores
// ---------------------------------------------------------------------------
__global__ __launch_bounds__(256) void attn_kernel()
{
    __shared__ float ks[NC * C], vs[NC * C];
    int b = blockIdx.y;
    int tid = threadIdx.x;
    for (int i = tid; i < NC * C; i += 256) {
        ks[i] = g_kbuf[(size_t)b * NC * C + i];
        vs[i] = g_vbuf[(size_t)b * NC * C + i];
    }
    __syncthreads();
    int h = tid >> 5, lane = tid & 31;
    int l0 = blockIdx.x * 128 + lane * 4;
    const __nv_bfloat16* qp = g_qqb + (size_t)b * C * HW + (size_t)(h * HD) * HW + l0;
    float a[4][NC];
    #pragma unroll
    for (int p = 0; p < 4; p++)
        #pragma unroll
        for (int n = 0; n < NC; n++) a[p][n] = 0.f;
    #pragma unroll
    for (int d = 0; d < HD; d++) {
        uint2 pk = *(const uint2*)(qp + (size_t)d * HW);
        __nv_bfloat162 q01 = *(__nv_bfloat162*)&pk.x;
        __nv_bfloat162 q23 = *(__nv_bfloat162*)&pk.y;
        float qv[4] = { __bfloat162float(q01.x), __bfloat162float(q01.y),
                        __bfloat162float(q23.x), __bfloat162float(q23.y) };
        const float* kd = ks + h * HD + d;
        #pragma unroll
        for (int n = 0; n < NC; n++) {
            float kv = kd[n * C];
            #pragma unroll
            for (int p = 0; p < 4; p++) a[p][n] += qv[p] * kv;
        }
    }
    float inv[4];
    #pragma unroll
    for (int p = 0; p < 4; p++) {
        float mn = 1e30f;
        #pragma unroll
        for (int n = 0; n < NC; n++) { a[p][n] *= SCALE; mn = fminf(mn, a[p][n]); }
        float s = 0.f;
        #pragma unroll
        for (int n = 0; n < NC; n++) { a[p][n] = expf(mn - a[p][n]); s += a[p][n]; }
        inv[p] = 1.f / s;
    }
    __nv_bfloat16* op = g_attb + (size_t)b * C * HW + (size_t)(h * HD) * HW + l0;
    #pragma unroll
    for (int d = 0; d < HD; d++) {
        const float* vd = vs + h * HD + d;
        float acc[4] = { 0.f, 0.f, 0.f, 0.f };
        #pragma unroll
        for (int n = 0; n < NC; n++) {
            float vv = vd[n * C];
            #pragma unroll
            for (int p = 0; p < 4; p++) acc[p] += a[p][n] * vv;
        }
        __nv_bfloat162 h0 = __floats2bfloat162_rn(acc[0] * inv[0], acc[1] * inv[1]);
        __nv_bfloat162 h1 = __floats2bfloat162_rn(acc[2] * inv[2], acc[3] * inv[3]);
        uint2 pk = { *(uint32_t*)&h0, *(uint32_t*)&h1 };
        *(uint2*)(op + (size_t)d * HW) = pk;
    }
}

// ---------------------------------------------------------------------------
// WMMA bf16 GEMM (R13 config, runtime K): Y = W @ X (+bias)(+res)
// ---------------------------------------------------------------------------
constexpr int LDA = 40;
constexpr int LDB = 264;
constexpr int A_BUF = 128 * LDA;
constexpr int B_BUF = 32 * LDB;
constexpr int GEMM_SMEM = (2 * A_BUF + 2 * B_BUF) * 2;

template <bool OUT_BF16, bool HAS_RES>
__global__ __launch_bounds__(256) void gemm_wmma(
    const __nv_bfloat16* __restrict__ Wb, const __nv_bfloat16* __restrict__ X,
    void* __restrict__ Y, const float* __restrict__ bias, const float* __restrict__ res,
    int M, int K)
{
    extern __shared__ char smem[];
    __nv_bfloat16* As = (__nv_bfloat16*)smem;
    __nv_bfloat16* Bs = As + 2 * A_BUF;
    uint32_t a_base = smem_u32(As);
    uint32_t b_base = smem_u32(Bs);

    int tid = threadIdx.x;
    int wid = tid >> 5;
    int wm = wid & 1;
    int wn = wid >> 1;
    int n0 = blockIdx.x * 256;
    int bm = blockIdx.y;
    int b  = blockIdx.z;

    const __nv_bfloat16* Ag = Wb + (size_t)(bm * 128) * K;
    const __nv_bfloat16* Xg = X + (size_t)b * K * HW + n0;

    wmma::fragment<wmma::accumulator, 16, 16, 16, float> acc[4][4];
    #pragma unroll
    for (int i = 0; i < 4; i++)
        #pragma unroll
        for (int j = 0; j < 4; j++) wmma::fill_fragment(acc[i][j], 0.f);

    int nk = K >> 5;

    auto load_tile = [&](int kt, int buf) {
        int k0 = kt * 32;
        #pragma unroll
        for (int i = 0; i < 2; i++) {
            int cid = i * 256 + tid;
            int r = cid >> 2, c8 = (cid & 3) * 8;
            cp_async16(a_base + (buf * A_BUF + r * LDA + c8) * 2,
                       Ag + (size_t)r * K + k0 + c8);
        }
        #pragma unroll
        for (int i = 0; i < 4; i++) {
            int cid = i * 256 + tid;
            int r = cid >> 5, c8 = (cid & 31) * 8;
            cp_async16(b_base + (buf * B_BUF + r * LDB + c8) * 2,
                       Xg + (size_t)(k0 + r) * HW + c8);
        }
        CP_COMMIT();
    };

    load_tile(0, 0);

    for (int kt = 0; kt < nk; kt++) {
        int buf = kt & 1;
        if (kt + 1 < nk) { load_tile(kt + 1, buf ^ 1); CP_WAIT(1); }
        else             { CP_WAIT(0); }
        __syncthreads();
        const __nv_bfloat16* Ab = As + buf * A_BUF;
        const __nv_bfloat16* Bb = Bs + buf * B_BUF;
        #pragma unroll
        for (int kk = 0; kk < 2; kk++) {
            wmma::fragment<wmma::matrix_a, 16, 16, 16, __nv_bfloat16, wmma::row_major> af[4];
            #pragma unroll
            for (int i = 0; i < 4; i++)
                wmma::load_matrix_sync(af[i], Ab + (wm * 64 + i * 16) * LDA + kk * 16, LDA);
            #pragma unroll
            for (int j = 0; j < 4; j++) {
                wmma::fragment<wmma::matrix_b, 16, 16, 16, __nv_bfloat16, wmma::row_major> bf;
                wmma::load_matrix_sync(bf, Bb + (kk * 16) * LDB + wn * 64 + j * 16, LDB);
                #pragma unroll
                for (int i = 0; i < 4; i++)
                    wmma::mma_sync(acc[i][j], af[i], bf, acc[i][j]);
            }
        }
        __syncthreads();
    }

    float* stage_w = (float*)smem + wid * (16 * 20);
    int lane = tid & 31;
    int rbase = bm * 128 + wm * 64;
    int cbase = n0 + wn * 64;
    size_t bb0 = (size_t)b * M * HW;
    int r = lane >> 1, cp4 = (lane & 1) * 8;
    #pragma unroll
    for (int i = 0; i < 4; i++) {
        #pragma unroll
        for (int j = 0; j < 4; j++) {
            wmma::store_matrix_sync(stage_w, acc[i][j], 20, wmma::mem_row_major);
            __syncwarp();
            int row = rbase + i * 16 + r;
            float bv = bias[row];
            size_t o = bb0 + (size_t)row * HW + cbase + j * 16 + cp4;
            float4 v0 = *(float4*)(stage_w + r * 20 + cp4);
            float4 v1 = *(float4*)(stage_w + r * 20 + cp4 + 4);
            v0.x += bv; v0.y += bv; v0.z += bv; v0.w += bv;
            v1.x += bv; v1.y += bv; v1.z += bv; v1.w += bv;
            if (HAS_RES) {
                float4 r0 = *(const float4*)(res + o);
                float4 r1 = *(const float4*)(res + o + 4);
                v0.x += r0.x; v0.y += r0.y; v0.z += r0.z; v0.w += r0.w;
                v1.x += r1.x; v1.y += r1.y; v1.z += r1.z; v1.w += r1.w;
            }
            if (OUT_BF16) {
                __nv_bfloat162 h0 = __floats2bfloat162_rn(v0.x, v0.y);
                __nv_bfloat162 h1 = __floats2bfloat162_rn(v0.z, v0.w);
                __nv_bfloat162 h2 = __floats2bfloat162_rn(v1.x, v1.y);
                __nv_bfloat162 h3 = __floats2bfloat162_rn(v1.z, v1.w);
                uint4 pk = { *(uint32_t*)&h0, *(uint32_t*)&h1, *(uint32_t*)&h2, *(uint32_t*)&h3 };
                *(uint4*)((__nv_bfloat16*)Y + o) = pk;
            } else {
                *(float4*)((float*)Y + o) = v0;
                *(float4*)((float*)Y + o + 4) = v1;
            }
            __syncwarp();
        }
    }
}

// ---------------------------------------------------------------------------
// Host launcher
// ---------------------------------------------------------------------------
extern "C" void kernel_launch(void* const* d_in, const int* in_sizes, int n_in,
                              void* d_out, int out_size)
{
    const float* low     = (const float*)d_in[0];
    const float* high    = (const float*)d_in[1];
    const float* gl      = (const float*)d_in[2];
    const float* bl      = (const float*)d_in[3];
    const float* gh      = (const float*)d_in[4];
    const float* bh      = (const float*)d_in[5];
    const float* gm      = (const float*)d_in[6];
    const float* bm      = (const float*)d_in[7];
    const float* w_q_dw  = (const float*)d_in[8];
    const float* b_q_dw  = (const float*)d_in[9];
    const float* w_q_pw  = (const float*)d_in[10];
    const float* b_q_pw  = (const float*)d_in[11];
    const float* w_ml1   = (const float*)d_in[12];
    const float* w_ml2   = (const float*)d_in[13];
    const float* w_align = (const float*)d_in[14];
    const float* w_kv    = (const float*)d_in[15];
    const float* b_kv    = (const float*)d_in[16];
    const float* memory  = (const float*)d_in[17];
    const float* w_proj  = (const float*)d_in[18];
    const float* b_proj  = (const float*)d_in[19];
    const float* w_mlp1  = (const float*)d_in[20];
    const float* b_mlp1  = (const float*)d_in[21];
    const float* w_mlpdw = (const float*)d_in[22];
    const float* b_mlpdw = (const float*)d_in[23];
    const float* w_mlp2  = (const float*)d_in[24];
    const float* b_mlp2  = (const float*)d_in[25];
    float* out = (float*)d_out;

    float *p_out;
    __nv_bfloat16 *p_queryb, *p_qdb, *p_qqb, *p_attb, *p_yb, *p_hidb, *p_hid2b;
    __nv_bfloat16 *p_wqpwb, *p_wprojb, *p_wmlp1b, *p_wmlp2b;
    cudaGetSymbolAddress((void**)&p_queryb, g_queryb);
    cudaGetSymbolAddress((void**)&p_out,   g_outb);
    cudaGetSymbolAddress((void**)&p_qdb,   g_qdb);
    cudaGetSymbolAddress((void**)&p_qqb,   g_qqb);
    cudaGetSymbolAddress((void**)&p_attb,  g_attb);
    cudaGetSymbolAddress((void**)&p_yb,    g_yb);
    cudaGetSymbolAddress((void**)&p_hidb,  g_hidb);
    cudaGetSymbolAddress((void**)&p_hid2b, g_hid2b);
    cudaGetSymbolAddress((void**)&p_wqpwb,  g_wqpwb);
    cudaGetSymbolAddress((void**)&p_wprojb, g_wprojb);
    cudaGetSymbolAddress((void**)&p_wmlp1b, g_wmlp1b);
    cudaGetSymbolAddress((void**)&p_wmlp2b, g_wmlp2b);

    cudaFuncSetAttribute(gemm_wmma<true,  false>, cudaFuncAttributeMaxDynamicSharedMemorySize, GEMM_SMEM);
    cudaFuncSetAttribute(gemm_wmma<false, true>,  cudaFuncAttributeMaxDynamicSharedMemorySize, GEMM_SMEM);

    // fused weight conversions (single launch)
    wconv_kernel<<<(2 * C * C + C4 * C + C * C4 + 255) / 256, 256>>>(w_q_pw, w_proj, w_mlp1, w_mlp2);

    // 1. LN + fuse
    ln_fuse_kernel<<<(B * HW + 255) / 256, 256>>>(low, high, gl, bl, gh, bh);
    // 2-3. mask path (R13 fused)
    weff_kernel<<<NC, C>>>(w_ml2, w_ml1);
    int smem = (NC * C + C * 64) * (int)sizeof(float);
    cudaFuncSetAttribute(mask_xa_kernel, cudaFuncAttributeMaxDynamicSharedMemorySize, smem);
    mask_xa_kernel<<<dim3(HW / 256, B), 128, smem>>>(w_align);
    // 4-6. softmax, cf, kv
    softmax_hw_kernel<<<B * NC, 256>>>();
    cf_kernel<<<dim3(C / 8, B), 256>>>();
    kv_kernel<<<B * NC, 512>>>(w_kv, b_kv, memory);
    // 7. query depthwise (vectorized tiled), then q_pw GEMM (bf16 out)
    dw3x3t_kernel<false><<<dim3(B * C, H / 8), 256>>>(p_queryb, p_qdb, w_q_dw, b_q_dw, C);
    gemm_wmma<true, false><<<dim3(HW / 256, C / 128, B), 256, GEMM_SMEM>>>(
        p_wqpwb, p_qdb, p_qqb, b_q_pw, nullptr, C, C);
    // 8. attention
    attn_kernel<<<dim3(HW / 128, B), 256>>>();
    // 9. proj + residual(low)
    gemm_wmma<false, true><<<dim3(HW / 256, C / 128, B), 256, GEMM_SMEM>>>(
        p_wprojb, p_attb, p_out, b_proj, low, C, C);
    // 10. FFN
    ln_bf_kernel<<<(B * HW + 255) / 256, 256>>>(p_out, p_yb, gm, bm);
    gemm_wmma<true, false><<<dim3(HW / 256, C4 / 128, B), 256, GEMM_SMEM>>>(
        p_wmlp1b, p_yb, p_hidb, b_mlp1, nullptr, C4, C);
    dw3x3t_kernel<true><<<dim3(B * C4, H / 8), 256>>>(p_hidb, p_hid2b, w_mlpdw, b_mlpdw, C4);
    gemm_wmma<false, true><<<dim3(HW / 256, C / 128, B), 256, GEMM_SMEM>>>(
        p_wmlp2b, p_hid2b, out, b_mlp2, p_out, C, C4);
}

// round 17
// speedup vs baseline: 1.0695x; 1.0065x over previous
#include <cuda_runtime.h>
#include <cuda_bf16.h>
#include <mma.h>
#include <math.h>
#include <cstdint>

using namespace nvcuda;

// ---------------------------------------------------------------------------
// Problem constants
// ---------------------------------------------------------------------------
namespace {
constexpr int B  = 4;
constexpr int C  = 256;
constexpr int H  = 128;
constexpr int W  = 128;
constexpr int HW = H * W;          // 16384
constexpr int NC = 19;
constexpr int HD = 32;
constexpr int C4 = 4 * C;          // 1024
constexpr float SCALE = 0.17677669529663687f;
constexpr float EPS = 1e-5f;
}

// ---------------------------------------------------------------------------
// Scratch
// ---------------------------------------------------------------------------
__device__ __nv_bfloat16 g_queryb[B * C * HW];
__device__ __nv_bfloat16 g_fusedb[B * C * HW];
__device__ float g_mask [B * NC * HW];
__device__ __nv_bfloat16 g_xab [B * C * HW];
__device__ float g_weff [NC * C];
__device__ float g_cf   [B * NC * C];
__device__ float g_kbuf [B * NC * C];
__device__ float g_vbuf [B * NC * C];
__device__ float g_outb [B * C * HW];
__device__ __nv_bfloat16 g_qdb  [B * C * HW];
__device__ __nv_bfloat16 g_qqb  [B * C * HW];
__device__ __nv_bfloat16 g_attb [B * C * HW];
__device__ __nv_bfloat16 g_yb   [B * C * HW];
__device__ __nv_bfloat16 g_hidb [B * C4 * HW];
__device__ __nv_bfloat16 g_hid2b[B * C4 * HW];
__device__ __nv_bfloat16 g_wqpwb [C * C];
__device__ __nv_bfloat16 g_wprojb[C * C];
__device__ __nv_bfloat16 g_wmlp1b[C4 * C];
__device__ __nv_bfloat16 g_wmlp2b[C * C4];
__device__ __nv_bfloat16 g_walignb[C * 64];

// ---------------------------------------------------------------------------
// helpers
// ---------------------------------------------------------------------------
__device__ __forceinline__ uint32_t smem_u32(const void* p) {
    uint32_t a;
    asm("{ .reg .u64 t; cvta.to.shared.u64 t, %1; cvt.u32.u64 %0, t; }" : "=r"(a) : "l"(p));
    return a;
}
__device__ __forceinline__ void cp_async16(uint32_t saddr, const void* gaddr) {
    asm volatile("cp.async.cg.shared.global [%0], [%1], 16;" :: "r"(saddr), "l"(gaddr));
}
#define CP_COMMIT() asm volatile("cp.async.commit_group;" ::: "memory")
#define CP_WAIT(n)  asm volatile("cp.async.wait_group %0;" :: "n"(n) : "memory")

// ---------------------------------------------------------------------------
// Fused fp32 -> bf16 conversion for all weight tensors (one launch)
// ---------------------------------------------------------------------------
__global__ void wconv_kernel(const float* __restrict__ w_q_pw, const float* __restrict__ w_proj,
                             const float* __restrict__ w_mlp1, const float* __restrict__ w_mlp2,
                             const float* __restrict__ w_align)
{
    int i = blockIdx.x * 256 + threadIdx.x;
    constexpr int N1 = C * C;
    constexpr int N2 = 2 * C * C;
    constexpr int N3 = N2 + C4 * C;
    constexpr int N4 = N3 + C * C4;
    constexpr int N5 = N4 + C * 64;
    if (i < N1)       g_wqpwb  [i]      = __float2bfloat16(w_q_pw[i]);
    else if (i < N2)  g_wprojb [i - N1] = __float2bfloat16(w_proj[i - N1]);
    else if (i < N3)  g_wmlp1b [i - N2] = __float2bfloat16(w_mlp1[i - N2]);
    else if (i < N4)  g_wmlp2b [i - N3] = __float2bfloat16(w_mlp2[i - N3]);
    else if (i < N5)  g_walignb[i - N4] = __float2bfloat16(w_align[i - N4]);
}

// ---------------------------------------------------------------------------
// K1: LN(low) -> query(bf16) ; LN(high) ; fused(bf16) = 0.5*(q + ln_high)
// ---------------------------------------------------------------------------
__global__ void ln_fuse_kernel(const float* __restrict__ low, const float* __restrict__ high,
                               const float* __restrict__ gl, const float* __restrict__ bl,
                               const float* __restrict__ gh, const float* __restrict__ bh)
{
    int pos = blockIdx.x * blockDim.x + threadIdx.x;
    if (pos >= B * HW) return;
    int b = pos / HW, l = pos % HW;
    const float* lp = low  + (size_t)b * C * HW + l;
    const float* hp = high + (size_t)b * C * HW + l;
    float s1 = 0.f, s2 = 0.f, t1 = 0.f, t2 = 0.f;
    #pragma unroll 8
    for (int c = 0; c < C; c++) {
        float a = lp[(size_t)c * HW]; s1 += a; s2 += a * a;
        float e = hp[(size_t)c * HW]; t1 += e; t2 += e * e;
    }
    float mu1 = s1 * (1.f / C), mu2 = t1 * (1.f / C);
    float i1 = rsqrtf(s2 * (1.f / C) - mu1 * mu1 + EPS);
    float i2 = rsqrtf(t2 * (1.f / C) - mu2 * mu2 + EPS);
    __nv_bfloat16* qo = g_queryb + (size_t)b * C * HW + l;
    __nv_bfloat16* fo = g_fusedb + (size_t)b * C * HW + l;
    #pragma unroll 8
    for (int c = 0; c < C; c++) {
        float q = (lp[(size_t)c * HW] - mu1) * i1 * gl[c] + bl[c];
        float k = (hp[(size_t)c * HW] - mu2) * i2 * gh[c] + bh[c];
        qo[(size_t)c * HW] = __float2bfloat16(q);
        fo[(size_t)c * HW] = __float2bfloat16(0.5f * (q + k));
    }
}

// LN over channels -> bf16 out
__global__ void ln_bf_kernel(const float* __restrict__ in, __nv_bfloat16* __restrict__ out,
                             const float* __restrict__ g, const float* __restrict__ bb)
{
    int pos = blockIdx.x * blockDim.x + threadIdx.x;
    if (pos >= B * HW) return;
    int b = pos / HW, l = pos % HW;
    const float* ip = in + (size_t)b * C * HW + l;
    float s1 = 0.f, s2 = 0.f;
    #pragma unroll 8
    for (int c = 0; c < C; c++) { float a = ip[(size_t)c * HW]; s1 += a; s2 += a * a; }
    float mu = s1 * (1.f / C);
    float iv = rsqrtf(s2 * (1.f / C) - mu * mu + EPS);
    __nv_bfloat16* op = out + (size_t)b * C * HW + l;
    #pragma unroll 8
    for (int c = 0; c < C; c++)
        op[(size_t)c * HW] = __float2bfloat16((ip[(size_t)c * HW] - mu) * iv * g[c] + bb[c]);
}

// ---------------------------------------------------------------------------
// K2: compose mask-path weights
// ---------------------------------------------------------------------------
__global__ void weff_kernel(const float* __restrict__ w_ml2, const float* __restrict__ w_ml1)
{
    int n = blockIdx.x, ci = threadIdx.x;
    int g = ci >> 6, jj = ci & 63;
    float acc = 0.f;
    #pragma unroll
    for (int j = 0; j < 64; j++) {
        int m = g * 64 + j;
        acc += w_ml2[n * C + m] * w_ml1[m * 64 + jj];
    }
    g_weff[n * C + ci] = acc;
}

// ---------------------------------------------------------------------------
// K3a: xa via tensor cores — per block: group g, M=64, N=256, K=64.
// grid = (HW/256, B, 4), block 128 (4 warps, each N=64 band).
// ---------------------------------------------------------------------------
__global__ __launch_bounds__(128) void xa_wmma_kernel()
{
    __shared__ __nv_bfloat16 Ws[64 * 72];    // 9216 B (epilogue stage overlays)
    __shared__ __nv_bfloat16 Xs[64 * 264];   // 33792 B
    int tid = threadIdx.x;
    int g = blockIdx.z, b = blockIdx.y;
    int n0 = blockIdx.x * 256;

    // W tile: 64(M=co) x 64(K=j), row-major, lda=72
    for (int i = tid; i < 64 * 64; i += 128) {
        int r = i >> 6, j = i & 63;
        Ws[r * 72 + j] = g_walignb[(g * 64 + r) * 64 + j];
    }
    // X tile: 64(K) x 256(N) from fused, ldb=264
    const __nv_bfloat16* fb = g_fusedb + (size_t)b * C * HW + (size_t)(g * 64) * HW + n0;
    uint32_t xbs = smem_u32(Xs);
    for (int i = tid; i < 64 * 32; i += 128) {
        int r = i >> 5, c8 = (i & 31) * 8;
        cp_async16(xbs + (r * 264 + c8) * 2, fb + (size_t)r * HW + c8);
    }
    CP_COMMIT(); CP_WAIT(0);
    __syncthreads();

    int wid = tid >> 5, lane = tid & 31;
    wmma::fragment<wmma::accumulator, 16, 16, 16, float> acc[4][4];
    #pragma unroll
    for (int i = 0; i < 4; i++)
        #pragma unroll
        for (int j = 0; j < 4; j++) wmma::fill_fragment(acc[i][j], 0.f);

    #pragma unroll
    for (int kk = 0; kk < 4; kk++) {
        wmma::fragment<wmma::matrix_a, 16, 16, 16, __nv_bfloat16, wmma::row_major> af[4];
        #pragma unroll
        for (int i = 0; i < 4; i++)
            wmma::load_matrix_sync(af[i], Ws + (i * 16) * 72 + kk * 16, 72);
        #pragma unroll
        for (int j = 0; j < 4; j++) {
            wmma::fragment<wmma::matrix_b, 16, 16, 16, __nv_bfloat16, wmma::row_major> bf;
            wmma::load_matrix_sync(bf, Xs + (kk * 16) * 264 + wid * 64 + j * 16, 264);
            #pragma unroll
            for (int i = 0; i < 4; i++)
                wmma::mma_sync(acc[i][j], af[i], bf, acc[i][j]);
        }
    }
    __syncthreads();

    // epilogue: stage (overlaid on Ws), bf16 out to g_xab
    float* stage_w = (float*)Ws + wid * (16 * 20);
    int r = lane >> 1, cp4 = (lane & 1) * 8;
    size_t obase = (size_t)b * C * HW + (size_t)(g * 64) * HW + n0 + wid * 64;
    #pragma unroll
    for (int i = 0; i < 4; i++) {
        #pragma unroll
        for (int j = 0; j < 4; j++) {
            wmma::store_matrix_sync(stage_w, acc[i][j], 20, wmma::mem_row_major);
            __syncwarp();
            size_t o = obase + (size_t)(i * 16 + r) * HW + j * 16 + cp4;
            float4 v0 = *(float4*)(stage_w + r * 20 + cp4);
            float4 v1 = *(float4*)(stage_w + r * 20 + cp4 + 4);
            __nv_bfloat162 h0 = __floats2bfloat162_rn(v0.x, v0.y);
            __nv_bfloat162 h1 = __floats2bfloat162_rn(v0.z, v0.w);
            __nv_bfloat162 h2 = __floats2bfloat162_rn(v1.x, v1.y);
            __nv_bfloat162 h3 = __floats2bfloat162_rn(v1.z, v1.w);
            uint4 pk = { *(uint32_t*)&h0, *(uint32_t*)&h1, *(uint32_t*)&h2, *(uint32_t*)&h3 };
            *(uint4*)(g_xab + o) = pk;
            __syncwarp();
        }
    }
}

// ---------------------------------------------------------------------------
// K3b: mask logits — streaming channel loop (R15-proven)
// grid = (HW/256, B), block 128, 2 positions/thread
// ---------------------------------------------------------------------------
__global__ __launch_bounds__(128) void mask_kernel()
{
    __shared__ float weff_s[NC * C];     // 19 KB
    int tid = threadIdx.x;
    for (int i = tid; i < NC * C; i += 128) weff_s[i] = g_weff[i];
    __syncthreads();
    int b = blockIdx.y;
    int l0 = blockIdx.x * 256 + tid;
    int l1 = l0 + 128;
    const __nv_bfloat16* fb = g_fusedb + (size_t)b * C * HW;
    float m0[NC], m1[NC];
    #pragma unroll
    for (int n = 0; n < NC; n++) { m0[n] = 0.f; m1[n] = 0.f; }
    #pragma unroll 4
    for (int c = 0; c < C; c++) {
        size_t co = (size_t)c * HW;
        float f0 = __bfloat162float(fb[co + l0]);
        float f1 = __bfloat162float(fb[co + l1]);
        #pragma unroll
        for (int n = 0; n < NC; n++) {
            float w = weff_s[n * C + c];
            m0[n] += w * f0; m1[n] += w * f1;
        }
    }
    #pragma unroll
    for (int n = 0; n < NC; n++) {
        size_t o = (size_t)b * NC * HW + (size_t)n * HW;
        g_mask[o + l0] = m0[n];
        g_mask[o + l1] = m1[n];
    }
}

// ---------------------------------------------------------------------------
// K4: spatial softmax over HW per (b,nc)
// ---------------------------------------------------------------------------
__global__ void softmax_hw_kernel()
{
    __shared__ float red[256];
    int row = blockIdx.x;
    float* p = g_mask + (size_t)row * HW;
    int tid = threadIdx.x;
    float m = -1e30f;
    for (int i = tid; i < HW; i += 256) m = fmaxf(m, p[i]);
    red[tid] = m; __syncthreads();
    for (int s = 128; s > 0; s >>= 1) { if (tid < s) red[tid] = fmaxf(red[tid], red[tid + s]); __syncthreads(); }
    m = red[0]; __syncthreads();
    float s = 0.f;
    for (int i = tid; i < HW; i += 256) s += expf(p[i] - m);
    red[tid] = s; __syncthreads();
    for (int st = 128; st > 0; st >>= 1) { if (tid < st) red[tid] += red[tid + st]; __syncthreads(); }
    float inv = 1.f / red[0];
    for (int i = tid; i < HW; i += 256) p[i] = expf(p[i] - m) * inv;
}

// ---------------------------------------------------------------------------
// K5: cf[b,n,c] — 8 channels per block
// ---------------------------------------------------------------------------
__global__ __launch_bounds__(256) void cf_kernel()
{
    int c0 = blockIdx.x * 8, b = blockIdx.y;
    int tid = threadIdx.x;
    const __nv_bfloat16* xp = g_xab + (size_t)(b * C + c0) * HW;
    const float* mp = g_mask + (size_t)b * NC * HW;
    float acc[NC][8];
    #pragma unroll
    for (int n = 0; n < NC; n++)
        #pragma unroll
        for (int cc = 0; cc < 8; cc++) acc[n][cc] = 0.f;
    for (int l = tid; l < HW; l += 256) {
        float xv[8];
        #pragma unroll
        for (int cc = 0; cc < 8; cc++) xv[cc] = __bfloat162float(xp[(size_t)cc * HW + l]);
        #pragma unroll
        for (int n = 0; n < NC; n++) {
            float m = mp[(size_t)n * HW + l];
            #pragma unroll
            for (int cc = 0; cc < 8; cc++) acc[n][cc] += m * xv[cc];
        }
    }
    __shared__ float red[8][NC * 8];
    int lane = tid & 31, wd = tid >> 5;
    #pragma unroll
    for (int n = 0; n < NC; n++)
        #pragma unroll
        for (int cc = 0; cc < 8; cc++) {
            float v = acc[n][cc];
            #pragma unroll
            for (int off = 16; off > 0; off >>= 1) v += __shfl_down_sync(0xFFFFFFFFu, v, off);
            if (lane == 0) red[wd][n * 8 + cc] = v;
        }
    __syncthreads();
    if (tid < NC * 8) {
        float s = 0.f;
        #pragma unroll
        for (int w = 0; w < 8; w++) s += red[w][tid];
        int n = tid >> 3, cc = tid & 7;
        g_cf[((size_t)b * NC + n) * C + c0 + cc] = s;
    }
}

// ---------------------------------------------------------------------------
// K6: memory-mix + kv projection
// ---------------------------------------------------------------------------
__global__ void kv_kernel(const float* __restrict__ w_kv, const float* __restrict__ b_kv,
                          const float* __restrict__ memory)
{
    int row = blockIdx.x;
    int n = row % NC;
    int tid = threadIdx.x;
    __shared__ float cfs[C];
    if (tid < C) cfs[tid] = 0.9f * g_cf[(size_t)row * C + tid] + 0.1f * memory[n * C + tid];
    __syncthreads();
    float acc = b_kv[tid];
    #pragma unroll 8
    for (int c = 0; c < C; c++) acc += cfs[c] * w_kv[(size_t)tid * C + c];
    if (tid < C) g_kbuf[(size_t)row * C + tid] = acc;
    else         g_vbuf[(size_t)row * C + tid - C] = acc;
}

// ---------------------------------------------------------------------------
// Depthwise 3x3 tiled, vectorized interior loads (uint4 = 8 bf16/LDG)
// ---------------------------------------------------------------------------
template <bool GELU>
__global__ __launch_bounds__(256) void dw3x3t_kernel(
    const __nv_bfloat16* __restrict__ in, __nv_bfloat16* __restrict__ out,
    const float* __restrict__ w, const float* __restrict__ bias, int Cn)
{
    __shared__ float tile[10][132];
    int bc = blockIdx.x;
    int y0 = blockIdx.y * 8;
    int c = bc % Cn;
    const __nv_bfloat16* ip = in + (size_t)bc * HW;
    int tid = threadIdx.x;

    if (tid < 160) {
        int ry = tid / 16, cx = (tid % 16) * 8;
        int gy = y0 - 1 + ry;
        float v[8] = { 0.f, 0.f, 0.f, 0.f, 0.f, 0.f, 0.f, 0.f };
        if (gy >= 0 && gy < H) {
            uint4 pk = *(const uint4*)(ip + gy * W + cx);
            const __nv_bfloat162* h2 = (const __nv_bfloat162*)&pk;
            #pragma unroll
            for (int t = 0; t < 4; t++) {
                float2 f = __bfloat1622float2(h2[t]);
                v[2 * t] = f.x; v[2 * t + 1] = f.y;
            }
        }
        #pragma unroll
        for (int k = 0; k < 8; k++) tile[ry][1 + cx + k] = v[k];
    } else if (tid < 200) {
        int e = tid - 160;
        int ry = e / 4, es = e % 4;
        int rx = (es == 0) ? 0 : (129 + es - 1);
        tile[ry][rx] = 0.f;
    }
    __syncthreads();

    float w0 = w[c*9+0], w1 = w[c*9+1], w2 = w[c*9+2];
    float w3 = w[c*9+3], w4 = w[c*9+4], w5 = w[c*9+5];
    float w6 = w[c*9+6], w7 = w[c*9+7], w8 = w[c*9+8];
    float bv = bias[c];
    int tx = tid & 31, ty = tid >> 5;
    int xb = tx * 4;
    float acc[4] = { bv, bv, bv, bv };
    {
        const float* r0 = tile[ty + 0];
        const float* r1 = tile[ty + 1];
        const float* r2 = tile[ty + 2];
        float v0[6], v1[6], v2[6];
        #pragma unroll
        for (int j = 0; j < 6; j++) { v0[j] = r0[xb+j]; v1[j] = r1[xb+j]; v2[j] = r2[xb+j]; }
        #pragma unroll
        for (int o = 0; o < 4; o++) {
            acc[o] += v0[o]*w0 + v0[o+1]*w1 + v0[o+2]*w2;
            acc[o] += v1[o]*w3 + v1[o+1]*w4 + v1[o+2]*w5;
            acc[o] += v2[o]*w6 + v2[o+1]*w7 + v2[o+2]*w8;
        }
    }
    if (GELU) {
        #pragma unroll
        for (int o = 0; o < 4; o++) {
            float x = acc[o];
            float u = 1.5957691216057308f * (x + 0.044715f * x * x * x);
            float s = 1.f / (1.f + __expf(-u));
            acc[o] = x * s;
        }
    }
    size_t obase = (size_t)bc * HW + (size_t)(y0 + ty) * W + xb;
    __nv_bfloat162 h0 = __floats2bfloat162_rn(acc[0], acc[1]);
    __nv_bfloat162 h1 = __floats2bfloat162_rn(acc[2], acc[3]);
    uint2 pk = { *(uint32_t*)&h0, *(uint32_t*)&h1 };
    *(uint2*)(out + obase) = pk;
}

// ---------------------------------------------------------------------------
// Attention: 4 positions/thread, vectorized q loads/stores
// ---------------------------------------------------------------------------
__global__ __launch_bounds__(256) void attn_kernel()
{
    __shared__ float ks[NC * C], vs[NC * C];
    int b = blockIdx.y;
    int tid = threadIdx.x;
    for (int i = tid; i < NC * C; i += 256) {
        ks[i] = g_kbuf[(size_t)b * NC * C + i];
        vs[i] = g_vbuf[(size_t)b * NC * C + i];
    }
    __syncthreads();
    int h = tid >> 5, lane = tid & 31;
    int l0 = blockIdx.x * 128 + lane * 4;
    const __nv_bfloat16* qp = g_qqb + (size_t)b * C * HW + (size_t)(h * HD) * HW + l0;
    float a[4][NC];
    #pragma unroll
    for (int p = 0; p < 4; p++)
        #pragma unroll
        for (int n = 0; n < NC; n++) a[p][n] = 0.f;
    #pragma unroll
    for (int d = 0; d < HD; d++) {
        uint2 pk = *(const uint2*)(qp + (size_t)d * HW);
        __nv_bfloat162 q01 = *(__nv_bfloat162*)&pk.x;
        __nv_bfloat162 q23 = *(__nv_bfloat162*)&pk.y;
        float qv[4] = { __bfloat162float(q01.x), __bfloat162float(q01.y),
                        __bfloat162float(q23.x), __bfloat162float(q23.y) };
        const float* kd = ks + h * HD + d;
        #pragma unroll
        for (int n = 0; n < NC; n++) {
            float kv = kd[n * C];
            #pragma unroll
            for (int p = 0; p < 4; p++) a[p][n] += qv[p] * kv;
        }
    }
    float inv[4];
    #pragma unroll
    for (int p = 0; p < 4; p++) {
        float mn = 1e30f;
        #pragma unroll
        for (int n = 0; n < NC; n++) { a[p][n] *= SCALE; mn = fminf(mn, a[p][n]); }
        float s = 0.f;
        #pragma unroll
        for (int n = 0; n < NC; n++) { a[p][n] = expf(mn - a[p][n]); s += a[p][n]; }
        inv[p] = 1.f / s;
    }
    __nv_bfloat16* op = g_attb + (size_t)b * C * HW + (size_t)(h * HD) * HW + l0;
    #pragma unroll
    for (int d = 0; d < HD; d++) {
        const float* vd = vs + h * HD + d;
        float acc[4] = { 0.f, 0.f, 0.f, 0.f };
        #pragma unroll
        for (int n = 0; n < NC; n++) {
            float vv = vd[n * C];
            #pragma unroll
            for (int p = 0; p < 4; p++) acc[p] += a[p][n] * vv;
        }
        __nv_bfloat162 h0 = __floats2bfloat162_rn(acc[0] * inv[0], acc[1] * inv[1]);
        __nv_bfloat162 h1 = __floats2bfloat162_rn(acc[2] * inv[2], acc[3] * inv[3]);
        uint2 pk = { *(uint32_t*)&h0, *(uint32_t*)&h1 };
        *(uint2*)(op + (size_t)d * HW) = pk;
    }
}

// ---------------------------------------------------------------------------
// WMMA bf16 GEMM (R13 config, runtime K): Y = W @ X (+bias)(+res)
// ---------------------------------------------------------------------------
constexpr int LDA = 40;
constexpr int LDB = 264;
constexpr int A_BUF = 128 * LDA;
constexpr int B_BUF = 32 * LDB;
constexpr int GEMM_SMEM = (2 * A_BUF + 2 * B_BUF) * 2;

template <bool OUT_BF16, bool HAS_RES>
__global__ __launch_bounds__(256) void gemm_wmma(
    const __nv_bfloat16* __restrict__ Wb, const __nv_bfloat16* __restrict__ X,
    void* __restrict__ Y, const float* __restrict__ bias, const float* __restrict__ res,
    int M, int K)
{
    extern __shared__ char smem[];
    __nv_bfloat16* As = (__nv_bfloat16*)smem;
    __nv_bfloat16* Bs = As + 2 * A_BUF;
    uint32_t a_base = smem_u32(As);
    uint32_t b_base = smem_u32(Bs);

    int tid = threadIdx.x;
    int wid = tid >> 5;
    int wm = wid & 1;
    int wn = wid >> 1;
    int n0 = blockIdx.x * 256;
    int bm = blockIdx.y;
    int b  = blockIdx.z;

    const __nv_bfloat16* Ag = Wb + (size_t)(bm * 128) * K;
    const __nv_bfloat16* Xg = X + (size_t)b * K * HW + n0;

    wmma::fragment<wmma::accumulator, 16, 16, 16, float> acc[4][4];
    #pragma unroll
    for (int i = 0; i < 4; i++)
        #pragma unroll
        for (int j = 0; j < 4; j++) wmma::fill_fragment(acc[i][j], 0.f);

    int nk = K >> 5;

    auto load_tile = [&](int kt, int buf) {
        int k0 = kt * 32;
        #pragma unroll
        for (int i = 0; i < 2; i++) {
            int cid = i * 256 + tid;
            int r = cid >> 2, c8 = (cid & 3) * 8;
            cp_async16(a_base + (buf * A_BUF + r * LDA + c8) * 2,
                       Ag + (size_t)r * K + k0 + c8);
        }
        #pragma unroll
        for (int i = 0; i < 4; i++) {
            int cid = i * 256 + tid;
            int r = cid >> 5, c8 = (cid & 31) * 8;
            cp_async16(b_base + (buf * B_BUF + r * LDB + c8) * 2,
                       Xg + (size_t)(k0 + r) * HW + c8);
        }
        CP_COMMIT();
    };

    load_tile(0, 0);

    for (int kt = 0; kt < nk; kt++) {
        int buf = kt & 1;
        if (kt + 1 < nk) { load_tile(kt + 1, buf ^ 1); CP_WAIT(1); }
        else             { CP_WAIT(0); }
        __syncthreads();
        const __nv_bfloat16* Ab = As + buf * A_BUF;
        const __nv_bfloat16* Bb = Bs + buf * B_BUF;
        #pragma unroll
        for (int kk = 0; kk < 2; kk++) {
            wmma::fragment<wmma::matrix_a, 16, 16, 16, __nv_bfloat16, wmma::row_major> af[4];
            #pragma unroll
            for (int i = 0; i < 4; i++)
                wmma::load_matrix_sync(af[i], Ab + (wm * 64 + i * 16) * LDA + kk * 16, LDA);
            #pragma unroll
            for (int j = 0; j < 4; j++) {
                wmma::fragment<wmma::matrix_b, 16, 16, 16, __nv_bfloat16, wmma::row_major> bf;
                wmma::load_matrix_sync(bf, Bb + (kk * 16) * LDB + wn * 64 + j * 16, LDB);
                #pragma unroll
                for (int i = 0; i < 4; i++)
                    wmma::mma_sync(acc[i][j], af[i], bf, acc[i][j]);
            }
        }
        __syncthreads();
    }

    float* stage_w = (float*)smem + wid * (16 * 20);
    int lane = tid & 31;
    int rbase = bm * 128 + wm * 64;
    int cbase = n0 + wn * 64;
    size_t bb0 = (size_t)b * M * HW;
    int r = lane >> 1, cp4 = (lane & 1) * 8;
    #pragma unroll
    for (int i = 0; i < 4; i++) {
        #pragma unroll
        for (int j = 0; j < 4; j++) {
            wmma::store_matrix_sync(stage_w, acc[i][j], 20, wmma::mem_row_major);
            __syncwarp();
            int row = rbase + i * 16 + r;
            float bv = bias[row];
            size_t o = bb0 + (size_t)row * HW + cbase + j * 16 + cp4;
            float4 v0 = *(float4*)(stage_w + r * 20 + cp4);
            float4 v1 = *(float4*)(stage_w + r * 20 + cp4 + 4);
            v0.x += bv; v0.y += bv; v0.z += bv; v0.w += bv;
            v1.x += bv; v1.y += bv; v1.z += bv; v1.w += bv;
            if (HAS_RES) {
                float4 r0 = *(const float4*)(res + o);
                float4 r1 = *(const float4*)(res + o + 4);
                v0.x += r0.x; v0.y += r0.y; v0.z += r0.z; v0.w += r0.w;
                v1.x += r1.x; v1.y += r1.y; v1.z += r1.z; v1.w += r1.w;
            }
            if (OUT_BF16) {
                __nv_bfloat162 h0 = __floats2bfloat162_rn(v0.x, v0.y);
                __nv_bfloat162 h1 = __floats2bfloat162_rn(v0.z, v0.w);
                __nv_bfloat162 h2 = __floats2bfloat162_rn(v1.x, v1.y);
                __nv_bfloat162 h3 = __floats2bfloat162_rn(v1.z, v1.w);
                uint4 pk = { *(uint32_t*)&h0, *(uint32_t*)&h1, *(uint32_t*)&h2, *(uint32_t*)&h3 };
                *(uint4*)((__nv_bfloat16*)Y + o) = pk;
            } else {
                *(float4*)((float*)Y + o) = v0;
                *(float4*)((float*)Y + o + 4) = v1;
            }
            __syncwarp();
        }
    }
}

// ---------------------------------------------------------------------------
// Host launcher
// ---------------------------------------------------------------------------
extern "C" void kernel_launch(void* const* d_in, const int* in_sizes, int n_in,
                              void* d_out, int out_size)
{
    const float* low     = (const float*)d_in[0];
    const float* high    = (const float*)d_in[1];
    const float* gl      = (const float*)d_in[2];
    const float* bl      = (const float*)d_in[3];
    const float* gh      = (const float*)d_in[4];
    const float* bh      = (const float*)d_in[5];
    const float* gm      = (const float*)d_in[6];
    const float* bm      = (const float*)d_in[7];
    const float* w_q_dw  = (const float*)d_in[8];
    const float* b_q_dw  = (const float*)d_in[9];
    const float* w_q_pw  = (const float*)d_in[10];
    const float* b_q_pw  = (const float*)d_in[11];
    const float* w_ml1   = (const float*)d_in[12];
    const float* w_ml2   = (const float*)d_in[13];
    const float* w_align = (const float*)d_in[14];
    const float* w_kv    = (const float*)d_in[15];
    const float* b_kv    = (const float*)d_in[16];
    const float* memory  = (const float*)d_in[17];
    const float* w_proj  = (const float*)d_in[18];
    const float* b_proj  = (const float*)d_in[19];
    const float* w_mlp1  = (const float*)d_in[20];
    const float* b_mlp1  = (const float*)d_in[21];
    const float* w_mlpdw = (const float*)d_in[22];
    const float* b_mlpdw = (const float*)d_in[23];
    const float* w_mlp2  = (const float*)d_in[24];
    const float* b_mlp2  = (const float*)d_in[25];
    float* out = (float*)d_out;

    float *p_out;
    __nv_bfloat16 *p_queryb, *p_qdb, *p_qqb, *p_attb, *p_yb, *p_hidb, *p_hid2b;
    __nv_bfloat16 *p_wqpwb, *p_wprojb, *p_wmlp1b, *p_wmlp2b;
    cudaGetSymbolAddress((void**)&p_queryb, g_queryb);
    cudaGetSymbolAddress((void**)&p_out,   g_outb);
    cudaGetSymbolAddress((void**)&p_qdb,   g_qdb);
    cudaGetSymbolAddress((void**)&p_qqb,   g_qqb);
    cudaGetSymbolAddress((void**)&p_attb,  g_attb);
    cudaGetSymbolAddress((void**)&p_yb,    g_yb);
    cudaGetSymbolAddress((void**)&p_hidb,  g_hidb);
    cudaGetSymbolAddress((void**)&p_hid2b, g_hid2b);
    cudaGetSymbolAddress((void**)&p_wqpwb,  g_wqpwb);
    cudaGetSymbolAddress((void**)&p_wprojb, g_wprojb);
    cudaGetSymbolAddress((void**)&p_wmlp1b, g_wmlp1b);
    cudaGetSymbolAddress((void**)&p_wmlp2b, g_wmlp2b);

    cudaFuncSetAttribute(gemm_wmma<true,  false>, cudaFuncAttributeMaxDynamicSharedMemorySize, GEMM_SMEM);
    cudaFuncSetAttribute(gemm_wmma<false, true>,  cudaFuncAttributeMaxDynamicSharedMemorySize, GEMM_SMEM);

    // fused weight conversions (single launch, now incl. w_align)
    wconv_kernel<<<(2 * C * C + C4 * C + C * C4 + C * 64 + 255) / 256, 256>>>(
        w_q_pw, w_proj, w_mlp1, w_mlp2, w_align);

    // 1. LN + fuse
    ln_fuse_kernel<<<(B * HW + 255) / 256, 256>>>(low, high, gl, bl, gh, bh);
    // 2-3. mask path: weff, then tensorized xa + streaming mask
    weff_kernel<<<NC, C>>>(w_ml2, w_ml1);
    xa_wmma_kernel<<<dim3(HW / 256, B, 4), 128>>>();
    mask_kernel<<<dim3(HW / 256, B), 128>>>();
    // 4-6. softmax, cf, kv
    softmax_hw_kernel<<<B * NC, 256>>>();
    cf_kernel<<<dim3(C / 8, B), 256>>>();
    kv_kernel<<<B * NC, 512>>>(w_kv, b_kv, memory);
    // 7. query depthwise (vectorized tiled), then q_pw GEMM (bf16 out)
    dw3x3t_kernel<false><<<dim3(B * C, H / 8), 256>>>(p_queryb, p_qdb, w_q_dw, b_q_dw, C);
    gemm_wmma<true, false><<<dim3(HW / 256, C / 128, B), 256, GEMM_SMEM>>>(
        p_wqpwb, p_qdb, p_qqb, b_q_pw, nullptr, C, C);
    // 8. attention
    attn_kernel<<<dim3(HW / 128, B), 256>>>();
    // 9. proj + residual(low)
    gemm_wmma<false, true><<<dim3(HW / 256, C / 128, B), 256, GEMM_SMEM>>>(
        p_wprojb, p_attb, p_out, b_proj, low, C, C);
    // 10. FFN
    ln_bf_kernel<<<(B * HW + 255) / 256, 256>>>(p_out, p_yb, gm, bm);
    gemm_wmma<true, false><<<dim3(HW / 256, C4 / 128, B), 256, GEMM_SMEM>>>(
        p_wmlp1b, p_yb, p_hidb, b_mlp1, nullptr, C4, C);
    dw3x3t_kernel<true><<<dim3(B * C4, H / 8), 256>>>(p_hidb, p_hid2b, w_mlpdw, b_mlpdw, C4);
    gemm_wmma<false, true><<<dim3(HW / 256, C / 128, B), 256, GEMM_SMEM>>>(
        p_wmlp2b, p_hid2b, out, b_mlp2, p_out, C, C4);
}